// round 11
// baseline (speedup 1.0000x reference)
#include <cuda_runtime.h>
#include <cuda_bf16.h>
#include <math.h>
#include <stdint.h>

#define N_NODES 2048
#define TXT     1386
#define HIDD    4096
#define CODE    64
#define XWORDS  44    // ceil(1386/32)
#define KPAD    1408  // 1386 padded to 64

// ===================== device scratch (no allocation allowed) ===============
__device__ __align__(16) unsigned g_xb[N_NODES * XWORDS];
__device__ __align__(16) int8_t   g_x8[(size_t)N_NODES * KPAD];      // x as s8 0/1
__device__ __align__(16) float    g_w [(size_t)N_NODES * N_NODES];   // fp32 adj (gc3)
__device__ __align__(16) int8_t   g_w8[(size_t)N_NODES * N_NODES];   // s8 adj (exact)
__device__ int                    g_deg[N_NODES];
__device__ __align__(16) float    g_P  [(size_t)N_NODES * HIDD];     // P1 / P2 fp32
__device__ __align__(16) float    g_F1 [(size_t)N_NODES * HIDD];     // feat1 fp32
__device__ __align__(16) int8_t   g_BThi[(size_t)HIDD * N_NODES];
__device__ __align__(16) int8_t   g_BTlo[(size_t)HIDD * N_NODES];
__device__ __align__(16) int8_t   g_Ahi[(size_t)N_NODES * HIDD];
__device__ __align__(16) int8_t   g_Alo[(size_t)N_NODES * HIDD];
__device__ __align__(16) int8_t   g_W2Thi[(size_t)HIDD * HIDD];
__device__ __align__(16) int8_t   g_W2Tlo[(size_t)HIDD * HIDD];
__device__ unsigned               g_mxP1[HIDD];
__device__ unsigned               g_mxP2[HIDD];
__device__ unsigned               g_mxW [HIDD];
__device__ float                  g_sb1[HIDD], g_sb2[HIDD], g_sw[HIDD];
__device__ float                  g_sa[N_NODES];
__device__ unsigned               g_amax[N_NODES];
__device__ float                  g_P3[(size_t)N_NODES * CODE];
__device__ float                  g_part[8 * (size_t)N_NODES * CODE];

// ===================== PTX helpers =========================================
__device__ __forceinline__ uint32_t smem_u32(const void* p) {
    uint32_t a;
    asm("{ .reg .u64 t; cvta.to.shared.u64 t, %1; cvt.u32.u64 %0, t; }" : "=r"(a) : "l"(p));
    return a;
}
__device__ __forceinline__ void cp16(uint32_t s, const void* g) {
    asm volatile("cp.async.cg.shared.global [%0], [%1], 16;"
        :: "r"(s), "l"(__cvta_generic_to_global(g)) : "memory");
}
#define CP_COMMIT() asm volatile("cp.async.commit_group;" ::: "memory")
#define CP_WAIT1()  asm volatile("cp.async.wait_group 1;" ::: "memory")
#define CP_WAIT0()  asm volatile("cp.async.wait_group 0;" ::: "memory")

__device__ __forceinline__ void ldmx4(uint32_t* r, uint32_t addr) {
    asm volatile("ldmatrix.sync.aligned.m8n8.x4.shared.b16 {%0,%1,%2,%3}, [%4];"
        : "=r"(r[0]), "=r"(r[1]), "=r"(r[2]), "=r"(r[3]) : "r"(addr));
}
__device__ __forceinline__ void imma16832(int* c, const uint32_t* a, const uint32_t* b) {
    asm volatile("mma.sync.aligned.m16n8k32.row.col.s32.s8.s8.s32 "
        "{%0,%1,%2,%3}, {%4,%5,%6,%7}, {%8,%9}, {%0,%1,%2,%3};"
        : "+r"(c[0]), "+r"(c[1]), "+r"(c[2]), "+r"(c[3])
        : "r"(a[0]), "r"(a[1]), "r"(a[2]), "r"(a[3]), "r"(b[0]), "r"(b[1]));
}

// ===================== fused prep: init + bitpack + s8 pack ================
__global__ void prep_all(const float* __restrict__ x) {
    int idx = blockIdx.x * 256 + threadIdx.x;
    if (idx < HIDD) { g_mxP1[idx] = 0; g_mxP2[idx] = 0; g_mxW[idx] = 0; }
    if (idx < N_NODES) { g_deg[idx] = 0; g_amax[idx] = 0; }
    if (idx < N_NODES * XWORDS) {
        int row = idx / XWORDS, w = idx - row * XWORDS;
        unsigned bits = 0;
        int base = w * 32;
        #pragma unroll 8
        for (int b = 0; b < 32; b++) {
            int c = base + b;
            if (c < TXT && x[(size_t)row * TXT + c] != 0.0f) bits |= (1u << b);
        }
        g_xb[idx] = bits;
    }
    if (idx < N_NODES * KPAD) {
        int row = idx / KPAD, col = idx - row * KPAD;
        int8_t v = 0;
        if (col < TXT && x[(size_t)row * TXT + col] != 0.0f) v = 1;
        g_x8[idx] = v;
    }
}

// ============ adjacency via exact int8 IMMA: S = x8 @ x8^T ================
// 2-stage pipeline, 2 CTAs/SM -> single wave for 256 CTAs.
__global__ __launch_bounds__(256, 2)
void gemm_adj(const int8_t* __restrict__ X, float* __restrict__ Wf,
              int8_t* __restrict__ W8, int* __restrict__ deg)
{
    extern __shared__ int8_t smem[];
    constexpr int SROW = 80;
    constexpr int TILE = 128 * SROW;
    constexpr int OFF_A = 0, OFF_B = TILE;
    constexpr int SS = 2 * TILE;      // 20480 per stage, 2 stages = 40960

    const int tid = threadIdx.x;
    const int w   = tid >> 5;
    const int l   = tid & 31;
    const int wm  = w >> 2;
    const int wn  = w & 3;
    const int bm  = blockIdx.y * 128;
    const int bn  = blockIdx.x * 128;
    const uint32_t smb = smem_u32(smem);

    auto load_stage = [&](int st, int k0) {
        const uint32_t sbase = smb + (uint32_t)st * SS;
        #pragma unroll
        for (int it = 0; it < 2; it++) {
            int idx = tid + it * 256;
            int r = idx >> 2, c = idx & 3;
            uint32_t so = (uint32_t)(r * SROW + c * 16);
            cp16(sbase + OFF_A + so, X + (size_t)(bm + r) * KPAD + k0 + c * 16);
            cp16(sbase + OFF_B + so, X + (size_t)(bn + r) * KPAD + k0 + c * 16);
        }
        CP_COMMIT();
    };

    int acc[4][4][4];
    #pragma unroll
    for (int i = 0; i < 4; i++)
        #pragma unroll
        for (int j = 0; j < 4; j++)
            #pragma unroll
            for (int e = 0; e < 4; e++) acc[i][j][e] = 0;

    const int NK = KPAD >> 6;   // 22
    load_stage(0, 0);
    load_stage(1, 64);

    const uint32_t a_off = (uint32_t)((wm * 64 + (l & 15)) * SROW + (l >> 4) * 16);
    const uint32_t b_off = (uint32_t)((wn * 32 + (l & 15)) * SROW + (l >> 4) * 16);

    for (int kt = 0; kt < NK; kt++) {
        if (kt >= NK - 1) { CP_WAIT0(); } else { CP_WAIT1(); }
        __syncthreads();

        const uint32_t sbase = smb + (uint32_t)((kt & 1) * SS);
        #pragma unroll
        for (int ks = 0; ks < 2; ks++) {
            const uint32_t ko = (uint32_t)ks * 32;
            uint32_t a[4][4];
            #pragma unroll
            for (int mt = 0; mt < 4; mt++)
                ldmx4(a[mt], sbase + OFF_A + a_off + (uint32_t)(mt * 16 * SROW) + ko);
            uint32_t b[4][2];
            #pragma unroll
            for (int np = 0; np < 2; np++) {
                uint32_t r[4];
                ldmx4(r, sbase + OFF_B + b_off + (uint32_t)(np * 16 * SROW) + ko);
                b[np * 2][0] = r[0]; b[np * 2 + 1][0] = r[1];
                b[np * 2][1] = r[2]; b[np * 2 + 1][1] = r[3];
            }
            #pragma unroll
            for (int mt = 0; mt < 4; mt++)
                #pragma unroll
                for (int nt = 0; nt < 4; nt++)
                    imma16832(acc[mt][nt], a[mt], b[nt]);
        }
        __syncthreads();
        if (kt + 2 < NK) load_stage(kt & 1, (kt + 2) << 6);
    }

    #pragma unroll
    for (int mt = 0; mt < 4; mt++) {
        const int row0 = bm + wm * 64 + mt * 16 + (l >> 2);
        const int row1 = row0 + 8;
        int d0 = 0, d1 = 0;
        #pragma unroll
        for (int nt = 0; nt < 4; nt++) {
            const int col = bn + wn * 32 + nt * 8 + (l & 3) * 2;
            int w0 = (acc[mt][nt][0] > 0) + (row0 == col);
            int w1 = (acc[mt][nt][1] > 0) + (row0 == col + 1);
            int w2 = (acc[mt][nt][2] > 0) + (row1 == col);
            int w3 = (acc[mt][nt][3] > 0) + (row1 == col + 1);
            *(float2*)(Wf + (size_t)row0 * N_NODES + col) = make_float2((float)w0, (float)w1);
            *(float2*)(Wf + (size_t)row1 * N_NODES + col) = make_float2((float)w2, (float)w3);
            char2 c01; c01.x = (char)w0; c01.y = (char)w1;
            char2 c23; c23.x = (char)w2; c23.y = (char)w3;
            *(char2*)(W8 + (size_t)row0 * N_NODES + col) = c01;
            *(char2*)(W8 + (size_t)row1 * N_NODES + col) = c23;
            d0 += w0 + w1;
            d1 += w2 + w3;
        }
        atomicAdd(&deg[row0], d0);
        atomicAdd(&deg[row1], d1);
    }
}

// ===================== xw1 + fused column-max ==============================
__global__ void xw1_kernel(const float* __restrict__ W1) {
    __shared__ int idxs[1392];
    __shared__ int nidx;
    const int row = blockIdx.x;
    const int tid = threadIdx.x;
    if (tid == 0) {
        int n = 0;
        #pragma unroll 4
        for (int w = 0; w < XWORDS; w++) {
            unsigned b = g_xb[row * XWORDS + w];
            while (b) { int bit = __ffs(b) - 1; idxs[n++] = w * 32 + bit; b &= b - 1; }
        }
        nidx = n;
    }
    __syncthreads();

    float acc[16];
    #pragma unroll
    for (int j = 0; j < 16; j++) acc[j] = 0.0f;
    const int n = nidx;
    for (int t = 0; t < n; t++) {
        const float* wr = W1 + (size_t)idxs[t] * HIDD + tid;
        #pragma unroll
        for (int j = 0; j < 16; j++) acc[j] += wr[j * 256];
    }
    float* out = g_P + (size_t)row * HIDD + tid;
    #pragma unroll
    for (int j = 0; j < 16; j++) {
        out[j * 256] = acc[j];
        atomicMax(&g_mxP1[tid + j * 256], __float_as_uint(fabsf(acc[j])));
    }
}

// column abs-max (standalone, for W2 only)
__global__ void colmax(const float* __restrict__ in, int R, int C, unsigned* __restrict__ mx) {
    int col = blockIdx.x * 256 + threadIdx.x;
    if (col >= C) return;
    int rchunk = R / gridDim.y;
    int r0 = blockIdx.y * rchunk;
    float m = 0.0f;
    for (int r = r0; r < r0 + rchunk; r++)
        m = fmaxf(m, fabsf(in[(size_t)r * C + col]));
    atomicMax(mx + col, __float_as_uint(m));
}

// transpose + 15-bit fixed-point split quantize: out[c][r] s8 hi/lo
__global__ void quantT(const float* __restrict__ in, int R, int C,
                       const unsigned* __restrict__ mxu,
                       int8_t* __restrict__ oh, int8_t* __restrict__ ol,
                       float* __restrict__ scale) {
    __shared__ float t[32][33];
    const int c0 = blockIdx.x * 32, r0 = blockIdx.y * 32;
    const int tx = threadIdx.x, ty = threadIdx.y;
    #pragma unroll
    for (int j = ty; j < 32; j += 8)
        t[j][tx] = in[(size_t)(r0 + j) * C + c0 + tx];
    __syncthreads();
    #pragma unroll
    for (int j = ty; j < 32; j += 8) {
        const int c = c0 + j;
        const float m = __uint_as_float(mxu[c]);
        const float inv = (m > 0.0f) ? (16256.0f / m) : 0.0f;
        float q = rintf(t[tx][j] * inv);
        float h = rintf(q * (1.0f / 128.0f));
        float l = q - 128.0f * h;
        size_t o = (size_t)c * R + r0 + tx;
        oh[o] = (int8_t)h;
        ol[o] = (int8_t)l;
        if (r0 == 0 && tx == 0) scale[c] = m * (1.0f / 16256.0f);
    }
}

// row-major quantize (A side): per-row scale from fused amax (uint bits)
__global__ void quantA(const float* __restrict__ in, const unsigned* __restrict__ amaxu,
                       int8_t* __restrict__ oh, int8_t* __restrict__ ol,
                       float* __restrict__ scale) {
    int idx = blockIdx.x * 256 + threadIdx.x;
    if (idx >= N_NODES * HIDD) return;
    int row = idx >> 12;
    int col = idx & (HIDD - 1);
    float m = __uint_as_float(amaxu[row]);
    float inv = (m > 0.0f) ? (16256.0f / m) : 0.0f;
    float q = rintf(in[idx] * inv);
    float h = rintf(q * (1.0f / 128.0f));
    oh[idx] = (int8_t)h;
    ol[idx] = (int8_t)(q - 128.0f * h);
    if (col == 0) scale[row] = m * (1.0f / 16256.0f);
}

// ===================== IMMA GEMM: C = w @ B  (A exact s8) ==================
// rinv folded: rs = 1/deg[row]. optional fused row abs-max of output.
template<bool RELU>
__global__ __launch_bounds__(256)
void gemm_wB(const int8_t* __restrict__ A,
             const int8_t* __restrict__ Bhi, const int8_t* __restrict__ Blo,
             float* __restrict__ C, int Kb, int NC,
             const float* __restrict__ sb, const int* __restrict__ deg,
             const float* __restrict__ bias, unsigned* __restrict__ amaxU)
{
    extern __shared__ int8_t smem[];
    constexpr int SROW = 80;
    constexpr int TILE = 128 * SROW;
    constexpr int OFF_A = 0, OFF_BH = TILE, OFF_BL = 2 * TILE;
    constexpr int SS = 3 * TILE;

    const int tid = threadIdx.x;
    const int w   = tid >> 5;
    const int l   = tid & 31;
    const int wm  = w >> 2;
    const int wn  = w & 3;
    const int bm  = blockIdx.y * 128;
    const int bn  = blockIdx.x * 128;
    const uint32_t smb = smem_u32(smem);

    auto load_stage = [&](int st, int k0) {
        const uint32_t sbase = smb + (uint32_t)st * SS;
        #pragma unroll
        for (int it = 0; it < 2; it++) {
            int idx = tid + it * 256;
            int r = idx >> 2, c = idx & 3;
            uint32_t so = (uint32_t)(r * SROW + c * 16);
            cp16(sbase + OFF_A  + so, A   + (size_t)(bm + r) * Kb + k0 + c * 16);
            cp16(sbase + OFF_BH + so, Bhi + (size_t)(bn + r) * Kb + k0 + c * 16);
            cp16(sbase + OFF_BL + so, Blo + (size_t)(bn + r) * Kb + k0 + c * 16);
        }
        CP_COMMIT();
    };

    int accH[4][4][4], accL[4][4][4];
    #pragma unroll
    for (int i = 0; i < 4; i++)
        #pragma unroll
        for (int j = 0; j < 4; j++)
            #pragma unroll
            for (int e = 0; e < 4; e++) { accH[i][j][e] = 0; accL[i][j][e] = 0; }

    const int NK = Kb >> 6;
    load_stage(0, 0);
    if (NK > 1) load_stage(1, 64);

    const uint32_t a_off = (uint32_t)((wm * 64 + (l & 15)) * SROW + (l >> 4) * 16);
    const uint32_t b_off = (uint32_t)((wn * 32 + (l & 15)) * SROW + (l >> 4) * 16);

    for (int kt = 0; kt < NK; kt++) {
        if (kt == NK - 1) { CP_WAIT0(); } else { CP_WAIT1(); }
        __syncthreads();
        if (kt + 2 < NK) load_stage((kt + 2) % 3, (kt + 2) << 6);

        const uint32_t sbase = smb + (uint32_t)((kt % 3) * SS);
        #pragma unroll
        for (int ks = 0; ks < 2; ks++) {
            const uint32_t ko = (uint32_t)ks * 32;
            uint32_t a[4][4];
            #pragma unroll
            for (int mt = 0; mt < 4; mt++)
                ldmx4(a[mt], sbase + OFF_A + a_off + (uint32_t)(mt * 16 * SROW) + ko);

            uint32_t bhi[4][2], blo[4][2];
            #pragma unroll
            for (int np = 0; np < 2; np++) {
                uint32_t r[4];
                ldmx4(r, sbase + OFF_BH + b_off + (uint32_t)(np * 16 * SROW) + ko);
                bhi[np * 2][0] = r[0]; bhi[np * 2 + 1][0] = r[1];
                bhi[np * 2][1] = r[2]; bhi[np * 2 + 1][1] = r[3];
                ldmx4(r, sbase + OFF_BL + b_off + (uint32_t)(np * 16 * SROW) + ko);
                blo[np * 2][0] = r[0]; blo[np * 2 + 1][0] = r[1];
                blo[np * 2][1] = r[2]; blo[np * 2 + 1][1] = r[3];
            }

            #pragma unroll
            for (int mt = 0; mt < 4; mt++)
                #pragma unroll
                for (int nt = 0; nt < 4; nt++)
                    imma16832(accH[mt][nt], a[mt], bhi[nt]);
            #pragma unroll
            for (int mt = 0; mt < 4; mt++)
                #pragma unroll
                for (int nt = 0; nt < 4; nt++)
                    imma16832(accL[mt][nt], a[mt], blo[nt]);
        }
        __syncthreads();
    }

    #pragma unroll
    for (int mt = 0; mt < 4; mt++) {
        const int row0 = bm + wm * 64 + mt * 16 + (l >> 2);
        const float rs0 = 1.0f / (float)deg[row0];
        const float rs1 = 1.0f / (float)deg[row0 + 8];
        float rm0 = 0.0f, rm1 = 0.0f;
        #pragma unroll
        for (int nt = 0; nt < 4; nt++) {
            const int col = bn + wn * 32 + nt * 8 + (l & 3) * 2;
            const float sb0 = sb[col], sb1 = sb[col + 1];
            const float bb0 = bias[col], bb1 = bias[col + 1];
            int c0 = accH[mt][nt][0] * 128 + accL[mt][nt][0];
            int c1 = accH[mt][nt][1] * 128 + accL[mt][nt][1];
            int c2 = accH[mt][nt][2] * 128 + accL[mt][nt][2];
            int c3 = accH[mt][nt][3] * 128 + accL[mt][nt][3];
            float v0 = (float)c0 * sb0 * rs0 + bb0;
            float v1 = (float)c1 * sb1 * rs0 + bb1;
            float v2 = (float)c2 * sb0 * rs1 + bb0;
            float v3 = (float)c3 * sb1 * rs1 + bb1;
            if (RELU) {
                v0 = fmaxf(v0, 0.0f); v1 = fmaxf(v1, 0.0f);
                v2 = fmaxf(v2, 0.0f); v3 = fmaxf(v3, 0.0f);
            }
            rm0 = fmaxf(rm0, fmaxf(fabsf(v0), fabsf(v1)));
            rm1 = fmaxf(rm1, fmaxf(fabsf(v2), fabsf(v3)));
            *(float2*)(C + (size_t)row0 * NC + col)       = make_float2(v0, v1);
            *(float2*)(C + (size_t)(row0 + 8) * NC + col) = make_float2(v2, v3);
        }
        if (amaxU) {
            atomicMax(amaxU + row0,     __float_as_uint(rm0));
            atomicMax(amaxU + row0 + 8, __float_as_uint(rm1));
        }
    }
}

// ===================== IMMA GEMM: C = A @ B^T (both split, 3 terms) ========
__global__ __launch_bounds__(256)
void gemm_AB(const int8_t* __restrict__ Ahi, const int8_t* __restrict__ Alo,
             const int8_t* __restrict__ Bhi, const int8_t* __restrict__ Blo,
             float* __restrict__ C, int Kb, int NC,
             const float* __restrict__ sa, const float* __restrict__ sbv,
             unsigned* __restrict__ cmaxU)
{
    extern __shared__ int8_t smem[];
    constexpr int SROW = 80;
    constexpr int TILE = 128 * SROW;
    constexpr int OFF_AH = 0, OFF_AL = TILE, OFF_BH = 2 * TILE, OFF_BL = 3 * TILE;
    constexpr int SS = 4 * TILE;

    const int tid = threadIdx.x;
    const int w   = tid >> 5;
    const int l   = tid & 31;
    const int wm  = w >> 2;
    const int wn  = w & 3;
    const int bm  = blockIdx.y * 128;
    const int bn  = blockIdx.x * 128;
    const uint32_t smb = smem_u32(smem);

    auto load_stage = [&](int st, int k0) {
        const uint32_t sbase = smb + (uint32_t)st * SS;
        #pragma unroll
        for (int it = 0; it < 2; it++) {
            int idx = tid + it * 256;
            int r = idx >> 2, c = idx & 3;
            uint32_t so = (uint32_t)(r * SROW + c * 16);
            cp16(sbase + OFF_AH + so, Ahi + (size_t)(bm + r) * Kb + k0 + c * 16);
            cp16(sbase + OFF_AL + so, Alo + (size_t)(bm + r) * Kb + k0 + c * 16);
            cp16(sbase + OFF_BH + so, Bhi + (size_t)(bn + r) * Kb + k0 + c * 16);
            cp16(sbase + OFF_BL + so, Blo + (size_t)(bn + r) * Kb + k0 + c * 16);
        }
        CP_COMMIT();
    };

    int accHH[4][4][4], accM[4][4][4];
    #pragma unroll
    for (int i = 0; i < 4; i++)
        #pragma unroll
        for (int j = 0; j < 4; j++)
            #pragma unroll
            for (int e = 0; e < 4; e++) { accHH[i][j][e] = 0; accM[i][j][e] = 0; }

    const int NK = Kb >> 6;
    load_stage(0, 0);
    if (NK > 1) load_stage(1, 64);

    const uint32_t a_off = (uint32_t)((wm * 64 + (l & 15)) * SROW + (l >> 4) * 16);
    const uint32_t b_off = (uint32_t)((wn * 32 + (l & 15)) * SROW + (l >> 4) * 16);

    for (int kt = 0; kt < NK; kt++) {
        if (kt == NK - 1) { CP_WAIT0(); } else { CP_WAIT1(); }
        __syncthreads();
        if (kt + 2 < NK) load_stage((kt + 2) % 3, (kt + 2) << 6);

        const uint32_t sbase = smb + (uint32_t)((kt % 3) * SS);
        #pragma unroll
        for (int ks = 0; ks < 2; ks++) {
            const uint32_t ko = (uint32_t)ks * 32;
            uint32_t ahi[4][4];
            #pragma unroll
            for (int mt = 0; mt < 4; mt++)
                ldmx4(ahi[mt], sbase + OFF_AH + a_off + (uint32_t)(mt * 16 * SROW) + ko);

            uint32_t bhi[4][2], blo[4][2];
            #pragma unroll
            for (int np = 0; np < 2; np++) {
                uint32_t r[4];
                ldmx4(r, sbase + OFF_BH + b_off + (uint32_t)(np * 16 * SROW) + ko);
                bhi[np * 2][0] = r[0]; bhi[np * 2 + 1][0] = r[1];
                bhi[np * 2][1] = r[2]; bhi[np * 2 + 1][1] = r[3];
                ldmx4(r, sbase + OFF_BL + b_off + (uint32_t)(np * 16 * SROW) + ko);
                blo[np * 2][0] = r[0]; blo[np * 2 + 1][0] = r[1];
                blo[np * 2][1] = r[2]; blo[np * 2 + 1][1] = r[3];
            }

            #pragma unroll
            for (int mt = 0; mt < 4; mt++)
                #pragma unroll
                for (int nt = 0; nt < 4; nt++)
                    imma16832(accHH[mt][nt], ahi[mt], bhi[nt]);
            #pragma unroll
            for (int mt = 0; mt < 4; mt++)
                #pragma unroll
                for (int nt = 0; nt < 4; nt++)
                    imma16832(accM[mt][nt], ahi[mt], blo[nt]);

            uint32_t alo[4][4];
            #pragma unroll
            for (int mt = 0; mt < 4; mt++)
                ldmx4(alo[mt], sbase + OFF_AL + a_off + (uint32_t)(mt * 16 * SROW) + ko);
            #pragma unroll
            for (int mt = 0; mt < 4; mt++)
                #pragma unroll
                for (int nt = 0; nt < 4; nt++)
                    imma16832(accM[mt][nt], alo[mt], bhi[nt]);
        }
        __syncthreads();
    }

    float cm[8];
    #pragma unroll
    for (int i = 0; i < 8; i++) cm[i] = 0.0f;

    #pragma unroll
    for (int mt = 0; mt < 4; mt++) {
        const int row0 = bm + wm * 64 + mt * 16 + (l >> 2);
        const float sa0 = sa[row0], sa1 = sa[row0 + 8];
        #pragma unroll
        for (int nt = 0; nt < 4; nt++) {
            const int col = bn + wn * 32 + nt * 8 + (l & 3) * 2;
            const float sb0 = sbv[col], sb1 = sbv[col + 1];
            float v0 = sa0 * sb0 * (16384.0f * (float)accHH[mt][nt][0] + 128.0f * (float)accM[mt][nt][0]);
            float v1 = sa0 * sb1 * (16384.0f * (float)accHH[mt][nt][1] + 128.0f * (float)accM[mt][nt][1]);
            float v2 = sa1 * sb0 * (16384.0f * (float)accHH[mt][nt][2] + 128.0f * (float)accM[mt][nt][2]);
            float v3 = sa1 * sb1 * (16384.0f * (float)accHH[mt][nt][3] + 128.0f * (float)accM[mt][nt][3]);
            cm[nt * 2]     = fmaxf(cm[nt * 2],     fmaxf(fabsf(v0), fabsf(v2)));
            cm[nt * 2 + 1] = fmaxf(cm[nt * 2 + 1], fmaxf(fabsf(v1), fabsf(v3)));
            *(float2*)(C + (size_t)row0 * NC + col)       = make_float2(v0, v1);
            *(float2*)(C + (size_t)(row0 + 8) * NC + col) = make_float2(v2, v3);
        }
    }
    if (cmaxU) {
        #pragma unroll
        for (int nt = 0; nt < 4; nt++) {
            const int col = bn + wn * 32 + nt * 8 + (l & 3) * 2;
            atomicMax(cmaxU + col,     __float_as_uint(cm[nt * 2]));
            atomicMax(cmaxU + col + 1, __float_as_uint(cm[nt * 2 + 1]));
        }
    }
}

// ===================== split-K FFMA sgemm (gc3, BK=32 coalesced) ===========
template<int V>
__device__ __forceinline__ void ldvec(float* d, const float* s) {
    if constexpr (V == 4) {
        *(float4*)d = *(const float4*)s;
    } else if constexpr (V == 2) {
        *(float2*)d = *(const float2*)s;
    } else {
        #pragma unroll
        for (int i = 0; i < V; i++) d[i] = s[i];
    }
}

template<int BM, int BN, int BK, int TM, int TN>
__global__ __launch_bounds__(256)
void sgemm_sk(const float* __restrict__ A, const float* __restrict__ B,
              float* __restrict__ C, int M, int N, int K, int lda)
{
    static_assert((BM / TM) * (BN / TN) == 256, "need 256 threads");
    constexpr int ALOAD = BM * BK / 256;
    constexpr int BLOAD = BK * BN / 256;

    __shared__ float As[2][BK * BM];
    __shared__ float Bs[2][BK * BN];

    const int s = blockIdx.z;
    A += (size_t)s * K;
    B += (size_t)s * K * N;
    C += (size_t)s * M * N;

    const int tid = threadIdx.x;
    const int bm  = blockIdx.y * BM;
    const int bn  = blockIdx.x * BN;
    const int tx  = tid % (BN / TN);
    const int ty  = tid / (BN / TN);

    #pragma unroll
    for (int l = 0; l < ALOAD; l++) {
        int idx = tid + l * 256;
        int r = idx / BK, c = idx % BK;
        As[0][c * BM + r] = A[(size_t)(bm + r) * lda + c];
    }
    #pragma unroll
    for (int l = 0; l < BLOAD; l++) {
        int idx = tid + l * 256;
        int r = idx / BN, c = idx % BN;
        Bs[0][r * BN + c] = B[(size_t)r * N + bn + c];
    }
    __syncthreads();

    float acc[TM * TN];
    #pragma unroll
    for (int i = 0; i < TM * TN; i++) acc[i] = 0.0f;

    float areg[ALOAD], breg[BLOAD];
    const int nk = K / BK;
    int st = 0;

    for (int kt = 0; kt < nk; kt++) {
        if (kt + 1 < nk) {
            const int k0 = (kt + 1) * BK;
            #pragma unroll
            for (int l = 0; l < ALOAD; l++) {
                int idx = tid + l * 256;
                int r = idx / BK, c = idx % BK;
                areg[l] = A[(size_t)(bm + r) * lda + k0 + c];
            }
            #pragma unroll
            for (int l = 0; l < BLOAD; l++) {
                int idx = tid + l * 256;
                int r = idx / BN, c = idx % BN;
                breg[l] = B[(size_t)(k0 + r) * N + bn + c];
            }
        }
        #pragma unroll
        for (int kk = 0; kk < BK; kk++) {
            float fa[TM], fb[TN];
            ldvec<TM>(fa, &As[st][kk * BM + ty * TM]);
            ldvec<TN>(fb, &Bs[st][kk * BN + tx * TN]);
            #pragma unroll
            for (int i = 0; i < TM; i++)
                #pragma unroll
                for (int j = 0; j < TN; j++)
                    acc[i * TN + j] += fa[i] * fb[j];
        }
        if (kt + 1 < nk) {
            st ^= 1;
            #pragma unroll
            for (int l = 0; l < ALOAD; l++) {
                int idx = tid + l * 256;
                int r = idx / BK, c = idx % BK;
                As[st][c * BM + r] = areg[l];
            }
            #pragma unroll
            for (int l = 0; l < BLOAD; l++) {
                int idx = tid + l * 256;
                int r = idx / BN, c = idx % BN;
                Bs[st][r * BN + c] = breg[l];
            }
            __syncthreads();
        }
    }

    const int row0 = bm + ty * TM;
    const int col0 = bn + tx * TN;
    #pragma unroll
    for (int i = 0; i < TM; i++)
        #pragma unroll
        for (int j = 0; j < TN; j++)
            C[(size_t)(row0 + i) * N + col0 + j] = acc[i * TN + j];
}

template<int MODE>
__global__ void sk_reduce(const float* __restrict__ part, int M, int S,
                          float* __restrict__ C, float* __restrict__ C2,
                          const int* __restrict__ deg, const float* __restrict__ bias) {
    int i = blockIdx.x * 256 + threadIdx.x;
    if (i >= M * CODE) return;
    int m = i >> 6, c = i & 63;
    float v = 0.0f;
    for (int s = 0; s < S; s++) v += part[(size_t)s * M * CODE + i];
    if (MODE == 3) {
        v = v * (1.0f / (float)deg[m]) + bias[c];
        C[i] = v;
        C2[i] = tanhf(v);
    } else {
        C[i] = v;
    }
}

// ===================== launch ==============================================
extern "C" void kernel_launch(void* const* d_in, const int* in_sizes, int n_in,
                              void* d_out, int out_size) {
    const float* x  = (const float*)d_in[0];
    const float* W1 = (const float*)d_in[1];
    const float* b1 = (const float*)d_in[2];
    const float* W2 = (const float*)d_in[3];
    const float* b2 = (const float*)d_in[4];
    const float* W3 = (const float*)d_in[5];
    const float* b3 = (const float*)d_in[6];

    void* p;
    float *w, *P, *F1, *P3, *part, *sb1, *sb2, *sw, *sa;
    int8_t *x8, *w8, *BThi, *BTlo, *Ahi, *Alo, *W2Thi, *W2Tlo;
    unsigned *mxP1, *mxP2, *mxW, *amaxU;
    int* deg;
    cudaGetSymbolAddress(&p, g_x8);    x8    = (int8_t*)p;
    cudaGetSymbolAddress(&p, g_w);     w     = (float*)p;
    cudaGetSymbolAddress(&p, g_w8);    w8    = (int8_t*)p;
    cudaGetSymbolAddress(&p, g_deg);   deg   = (int*)p;
    cudaGetSymbolAddress(&p, g_P);     P     = (float*)p;
    cudaGetSymbolAddress(&p, g_F1);    F1    = (float*)p;
    cudaGetSymbolAddress(&p, g_P3);    P3    = (float*)p;
    cudaGetSymbolAddress(&p, g_part);  part  = (float*)p;
    cudaGetSymbolAddress(&p, g_BThi);  BThi  = (int8_t*)p;
    cudaGetSymbolAddress(&p, g_BTlo);  BTlo  = (int8_t*)p;
    cudaGetSymbolAddress(&p, g_Ahi);   Ahi   = (int8_t*)p;
    cudaGetSymbolAddress(&p, g_Alo);   Alo   = (int8_t*)p;
    cudaGetSymbolAddress(&p, g_W2Thi); W2Thi = (int8_t*)p;
    cudaGetSymbolAddress(&p, g_W2Tlo); W2Tlo = (int8_t*)p;
    cudaGetSymbolAddress(&p, g_mxP1);  mxP1  = (unsigned*)p;
    cudaGetSymbolAddress(&p, g_mxP2);  mxP2  = (unsigned*)p;
    cudaGetSymbolAddress(&p, g_mxW);   mxW   = (unsigned*)p;
    cudaGetSymbolAddress(&p, g_sb1);   sb1   = (float*)p;
    cudaGetSymbolAddress(&p, g_sb2);   sb2   = (float*)p;
    cudaGetSymbolAddress(&p, g_sw);    sw    = (float*)p;
    cudaGetSymbolAddress(&p, g_sa);    sa    = (float*)p;
    cudaGetSymbolAddress(&p, g_amax);  amaxU = (unsigned*)p;

    float* featOut = (float*)d_out;
    float* hidOut  = featOut + (size_t)N_NODES * HIDD;
    float* codeOut = hidOut  + (size_t)N_NODES * CODE;

    constexpr int SMEM_ADJ = 2 * 2 * 128 * 80;  // 40960 (2 stages -> 2 CTAs/SM)
    constexpr int SMEM_WB  = 3 * 3 * 128 * 80;  // 92160
    constexpr int SMEM_AB  = 3 * 4 * 128 * 80;  // 122880
    cudaFuncSetAttribute(gemm_adj,       cudaFuncAttributeMaxDynamicSharedMemorySize, SMEM_ADJ);
    cudaFuncSetAttribute(gemm_wB<false>, cudaFuncAttributeMaxDynamicSharedMemorySize, SMEM_WB);
    cudaFuncSetAttribute(gemm_wB<true>,  cudaFuncAttributeMaxDynamicSharedMemorySize, SMEM_WB);
    cudaFuncSetAttribute(gemm_AB,        cudaFuncAttributeMaxDynamicSharedMemorySize, SMEM_AB);

    // fused prep + adjacency (exact IMMA)
    prep_all<<<(N_NODES * KPAD + 255) / 256, 256>>>(x);
    gemm_adj<<<dim3(N_NODES / 128, N_NODES / 128), 256, SMEM_ADJ>>>(x8, w, w8, deg);

    // W2 quantization
    colmax<<<dim3(HIDD / 256, 16), 256>>>(W2, HIDD, HIDD, mxW);
    quantT<<<dim3(HIDD / 32, HIDD / 32), dim3(32, 8)>>>(W2, HIDD, HIDD, mxW, W2Thi, W2Tlo, sw);

    // gc1: P1 = x@W1 (fused colmax) ; quantize P1^T ; feat1 = (w@P1)/deg+b1 (fused rowmax)
    xw1_kernel<<<N_NODES, 256>>>(W1);
    quantT<<<dim3(HIDD / 32, N_NODES / 32), dim3(32, 8)>>>(P, N_NODES, HIDD, mxP1, BThi, BTlo, sb1);
    gemm_wB<false><<<dim3(HIDD / 128, N_NODES / 128), 256, SMEM_WB>>>(
        w8, BThi, BTlo, F1, N_NODES, HIDD, sb1, deg, b1, amaxU);

    // gc2: quantize feat1 rows ; P2 = f1q@W2q (fused colmax) ; quantize P2^T ;
    //      feat = relu((w@P2)/deg+b2) -> d_out
    quantA<<<(N_NODES * HIDD + 255) / 256, 256>>>(F1, amaxU, Ahi, Alo, sa);
    gemm_AB<<<dim3(HIDD / 128, N_NODES / 128), 256, SMEM_AB>>>(
        Ahi, Alo, W2Thi, W2Tlo, P, HIDD, HIDD, sa, sw, mxP2);
    quantT<<<dim3(HIDD / 32, N_NODES / 32), dim3(32, 8)>>>(P, N_NODES, HIDD, mxP2, BThi, BTlo, sb2);
    gemm_wB<true><<<dim3(HIDD / 128, N_NODES / 128), 256, SMEM_WB>>>(
        w8, BThi, BTlo, featOut, N_NODES, HIDD, sb2, deg, b2, nullptr);

    // gc3 (fp32 split-K, BK=32 coalesced)
    sgemm_sk<64, 64, 32, 4, 4><<<dim3(1, N_NODES / 64, 8), 256>>>(
        featOut, W3, part, N_NODES, CODE, HIDD / 8, HIDD);
    sk_reduce<0><<<(N_NODES * CODE + 255) / 256, 256>>>(
        part, N_NODES, 8, P3, nullptr, nullptr, nullptr);
    sgemm_sk<64, 64, 32, 4, 4><<<dim3(1, N_NODES / 64, 8), 256>>>(
        w, P3, part, N_NODES, CODE, N_NODES / 8, N_NODES);
    sk_reduce<3><<<(N_NODES * CODE + 255) / 256, 256>>>(
        part, N_NODES, 8, hidOut, codeOut, deg, b3);
}

// round 13
// speedup vs baseline: 1.0480x; 1.0480x over previous
#include <cuda_runtime.h>
#include <cuda_bf16.h>
#include <math.h>
#include <stdint.h>

#define N_NODES 2048
#define TXT     1386
#define HIDD    4096
#define CODE    64
#define XWORDS  44    // ceil(1386/32)
#define KPAD    1408  // 1386 padded to 64

// ===================== device scratch (no allocation allowed) ===============
__device__ __align__(16) unsigned g_xb[N_NODES * XWORDS];
__device__ __align__(16) int8_t   g_x8[(size_t)N_NODES * KPAD];      // x as s8 0/1
__device__ __align__(16) float    g_w [(size_t)N_NODES * N_NODES];   // fp32 adj (gc3)
__device__ __align__(16) int8_t   g_w8[(size_t)N_NODES * N_NODES];   // s8 adj (exact)
__device__ int                    g_deg[N_NODES];
__device__ __align__(16) float    g_P  [(size_t)N_NODES * HIDD];     // P1 / P2 fp32
__device__ __align__(16) float    g_F1 [(size_t)N_NODES * HIDD];     // feat1 fp32
__device__ __align__(16) int8_t   g_BThi[(size_t)HIDD * N_NODES];
__device__ __align__(16) int8_t   g_BTlo[(size_t)HIDD * N_NODES];
__device__ __align__(16) int8_t   g_Ahi[(size_t)N_NODES * HIDD];
__device__ __align__(16) int8_t   g_Alo[(size_t)N_NODES * HIDD];
__device__ __align__(16) int8_t   g_W2Thi[(size_t)HIDD * HIDD];
__device__ __align__(16) int8_t   g_W2Tlo[(size_t)HIDD * HIDD];
__device__ unsigned               g_mxP1[HIDD];
__device__ unsigned               g_mxP2[HIDD];
__device__ unsigned               g_mxW [HIDD];
__device__ float                  g_sb1[HIDD], g_sb2[HIDD], g_sw[HIDD];
__device__ float                  g_sa[N_NODES];
__device__ unsigned               g_amax[N_NODES];
__device__ float                  g_P3[(size_t)N_NODES * CODE];
__device__ float                  g_part[8 * (size_t)N_NODES * CODE];

// ===================== PTX helpers =========================================
__device__ __forceinline__ uint32_t smem_u32(const void* p) {
    uint32_t a;
    asm("{ .reg .u64 t; cvta.to.shared.u64 t, %1; cvt.u32.u64 %0, t; }" : "=r"(a) : "l"(p));
    return a;
}
__device__ __forceinline__ void cp16(uint32_t s, const void* g) {
    asm volatile("cp.async.cg.shared.global [%0], [%1], 16;"
        :: "r"(s), "l"(__cvta_generic_to_global(g)) : "memory");
}
#define CP_COMMIT() asm volatile("cp.async.commit_group;" ::: "memory")
#define CP_WAIT1()  asm volatile("cp.async.wait_group 1;" ::: "memory")
#define CP_WAIT0()  asm volatile("cp.async.wait_group 0;" ::: "memory")

__device__ __forceinline__ void ldmx4(uint32_t* r, uint32_t addr) {
    asm volatile("ldmatrix.sync.aligned.m8n8.x4.shared.b16 {%0,%1,%2,%3}, [%4];"
        : "=r"(r[0]), "=r"(r[1]), "=r"(r[2]), "=r"(r[3]) : "r"(addr));
}
__device__ __forceinline__ void imma16832(int* c, const uint32_t* a, const uint32_t* b) {
    asm volatile("mma.sync.aligned.m16n8k32.row.col.s32.s8.s8.s32 "
        "{%0,%1,%2,%3}, {%4,%5,%6,%7}, {%8,%9}, {%0,%1,%2,%3};"
        : "+r"(c[0]), "+r"(c[1]), "+r"(c[2]), "+r"(c[3])
        : "r"(a[0]), "r"(a[1]), "r"(a[2]), "r"(a[3]), "r"(b[0]), "r"(b[1]));
}

// ===================== fused prep: init + bitpack + s8 pack ================
__global__ void prep_all(const float* __restrict__ x) {
    int idx = blockIdx.x * 256 + threadIdx.x;
    if (idx < HIDD) { g_mxP1[idx] = 0; g_mxP2[idx] = 0; g_mxW[idx] = 0; }
    if (idx < N_NODES) { g_deg[idx] = 0; g_amax[idx] = 0; }
    if (idx < N_NODES * XWORDS) {
        int row = idx / XWORDS, w = idx - row * XWORDS;
        unsigned bits = 0;
        int base = w * 32;
        #pragma unroll 8
        for (int b = 0; b < 32; b++) {
            int c = base + b;
            if (c < TXT && x[(size_t)row * TXT + c] != 0.0f) bits |= (1u << b);
        }
        g_xb[idx] = bits;
    }
    if (idx < N_NODES * KPAD) {
        int row = idx / KPAD, col = idx - row * KPAD;
        int8_t v = 0;
        if (col < TXT && x[(size_t)row * TXT + col] != 0.0f) v = 1;
        g_x8[idx] = v;
    }
}

// ============ adjacency via exact int8 IMMA: S = x8 @ x8^T ================
__global__ __launch_bounds__(256, 2)
void gemm_adj(const int8_t* __restrict__ X, float* __restrict__ Wf,
              int8_t* __restrict__ W8, int* __restrict__ deg)
{
    extern __shared__ int8_t smem[];
    constexpr int SROW = 80;
    constexpr int TILE = 128 * SROW;
    constexpr int OFF_A = 0, OFF_B = TILE;
    constexpr int SS = 2 * TILE;

    const int tid = threadIdx.x;
    const int w   = tid >> 5;
    const int l   = tid & 31;
    const int wm  = w >> 2;
    const int wn  = w & 3;
    const int bm  = blockIdx.y * 128;
    const int bn  = blockIdx.x * 128;
    const uint32_t smb = smem_u32(smem);

    auto load_stage = [&](int st, int k0) {
        const uint32_t sbase = smb + (uint32_t)st * SS;
        #pragma unroll
        for (int it = 0; it < 2; it++) {
            int idx = tid + it * 256;
            int r = idx >> 2, c = idx & 3;
            uint32_t so = (uint32_t)(r * SROW + c * 16);
            cp16(sbase + OFF_A + so, X + (size_t)(bm + r) * KPAD + k0 + c * 16);
            cp16(sbase + OFF_B + so, X + (size_t)(bn + r) * KPAD + k0 + c * 16);
        }
        CP_COMMIT();
    };

    int acc[4][4][4];
    #pragma unroll
    for (int i = 0; i < 4; i++)
        #pragma unroll
        for (int j = 0; j < 4; j++)
            #pragma unroll
            for (int e = 0; e < 4; e++) acc[i][j][e] = 0;

    const int NK = KPAD >> 6;   // 22
    load_stage(0, 0);
    load_stage(1, 64);

    const uint32_t a_off = (uint32_t)((wm * 64 + (l & 15)) * SROW + (l >> 4) * 16);
    const uint32_t b_off = (uint32_t)((wn * 32 + (l & 15)) * SROW + (l >> 4) * 16);

    for (int kt = 0; kt < NK; kt++) {
        if (kt >= NK - 1) { CP_WAIT0(); } else { CP_WAIT1(); }
        __syncthreads();

        const uint32_t sbase = smb + (uint32_t)((kt & 1) * SS);
        #pragma unroll
        for (int ks = 0; ks < 2; ks++) {
            const uint32_t ko = (uint32_t)ks * 32;
            uint32_t a[4][4];
            #pragma unroll
            for (int mt = 0; mt < 4; mt++)
                ldmx4(a[mt], sbase + OFF_A + a_off + (uint32_t)(mt * 16 * SROW) + ko);
            uint32_t b[4][2];
            #pragma unroll
            for (int np = 0; np < 2; np++) {
                uint32_t r[4];
                ldmx4(r, sbase + OFF_B + b_off + (uint32_t)(np * 16 * SROW) + ko);
                b[np * 2][0] = r[0]; b[np * 2 + 1][0] = r[1];
                b[np * 2][1] = r[2]; b[np * 2 + 1][1] = r[3];
            }
            #pragma unroll
            for (int mt = 0; mt < 4; mt++)
                #pragma unroll
                for (int nt = 0; nt < 4; nt++)
                    imma16832(acc[mt][nt], a[mt], b[nt]);
        }
        __syncthreads();
        if (kt + 2 < NK) load_stage(kt & 1, (kt + 2) << 6);
    }

    #pragma unroll
    for (int mt = 0; mt < 4; mt++) {
        const int row0 = bm + wm * 64 + mt * 16 + (l >> 2);
        const int row1 = row0 + 8;
        int d0 = 0, d1 = 0;
        #pragma unroll
        for (int nt = 0; nt < 4; nt++) {
            const int col = bn + wn * 32 + nt * 8 + (l & 3) * 2;
            int w0 = (acc[mt][nt][0] > 0) + (row0 == col);
            int w1 = (acc[mt][nt][1] > 0) + (row0 == col + 1);
            int w2 = (acc[mt][nt][2] > 0) + (row1 == col);
            int w3 = (acc[mt][nt][3] > 0) + (row1 == col + 1);
            *(float2*)(Wf + (size_t)row0 * N_NODES + col) = make_float2((float)w0, (float)w1);
            *(float2*)(Wf + (size_t)row1 * N_NODES + col) = make_float2((float)w2, (float)w3);
            char2 c01; c01.x = (char)w0; c01.y = (char)w1;
            char2 c23; c23.x = (char)w2; c23.y = (char)w3;
            *(char2*)(W8 + (size_t)row0 * N_NODES + col) = c01;
            *(char2*)(W8 + (size_t)row1 * N_NODES + col) = c23;
            d0 += w0 + w1;
            d1 += w2 + w3;
        }
        atomicAdd(&deg[row0], d0);
        atomicAdd(&deg[row1], d1);
    }
}

// ===================== xw1 + fused column-max ==============================
__global__ void xw1_kernel(const float* __restrict__ W1) {
    __shared__ int idxs[1392];
    __shared__ int nidx;
    const int row = blockIdx.x;
    const int tid = threadIdx.x;
    if (tid == 0) {
        int n = 0;
        #pragma unroll 4
        for (int w = 0; w < XWORDS; w++) {
            unsigned b = g_xb[row * XWORDS + w];
            while (b) { int bit = __ffs(b) - 1; idxs[n++] = w * 32 + bit; b &= b - 1; }
        }
        nidx = n;
    }
    __syncthreads();

    float acc[16];
    #pragma unroll
    for (int j = 0; j < 16; j++) acc[j] = 0.0f;
    const int n = nidx;
    for (int t = 0; t < n; t++) {
        const float* wr = W1 + (size_t)idxs[t] * HIDD + tid;
        #pragma unroll
        for (int j = 0; j < 16; j++) acc[j] += wr[j * 256];
    }
    float* out = g_P + (size_t)row * HIDD + tid;
    #pragma unroll
    for (int j = 0; j < 16; j++) {
        out[j * 256] = acc[j];
        atomicMax(&g_mxP1[tid + j * 256], __float_as_uint(fabsf(acc[j])));
    }
}

// column abs-max (standalone, for W2 only)
__global__ void colmax(const float* __restrict__ in, int R, int C, unsigned* __restrict__ mx) {
    int col = blockIdx.x * 256 + threadIdx.x;
    if (col >= C) return;
    int rchunk = R / gridDim.y;
    int r0 = blockIdx.y * rchunk;
    float m = 0.0f;
    for (int r = r0; r < r0 + rchunk; r++)
        m = fmaxf(m, fabsf(in[(size_t)r * C + col]));
    atomicMax(mx + col, __float_as_uint(m));
}

// transpose + 15-bit split quantize, COALESCED STORES:
// tile 32 cols x 128 rows; each thread packs 16 consecutive-r int8 -> uint4.
// grid (C/32, R/128), block 256.
__global__ void quantT(const float* __restrict__ in, int R, int C,
                       const unsigned* __restrict__ mxu,
                       int8_t* __restrict__ oh, int8_t* __restrict__ ol,
                       float* __restrict__ scale) {
    __shared__ float t[32][129];                 // [col][row], pad
    const int c0 = blockIdx.x * 32, r0 = blockIdx.y * 128;
    const int tid = threadIdx.x;
    #pragma unroll
    for (int i = 0; i < 16; i++) {
        int e = tid + i * 256;
        int r = e >> 5, c = e & 31;              // warp: fixed r, c 0..31 -> 128B coalesced
        t[c][r] = in[(size_t)(r0 + r) * C + c0 + c];
    }
    __syncthreads();

    const int cc = tid >> 3;                     // 0..31
    const int rs = (tid & 7) * 16;               // 0,16,...,112
    const int c  = c0 + cc;
    const float m = __uint_as_float(mxu[c]);
    const float inv = (m > 0.0f) ? (16256.0f / m) : 0.0f;

    uint32_t wh[4], wl[4];
    #pragma unroll
    for (int k4 = 0; k4 < 4; k4++) {
        uint32_t ph = 0, pl = 0;
        #pragma unroll
        for (int j = 0; j < 4; j++) {
            float q = rintf(t[cc][rs + k4 * 4 + j] * inv);
            float h = rintf(q * (1.0f / 128.0f));
            float lo = q - 128.0f * h;
            ph |= ((uint32_t)(uint8_t)(int8_t)h) << (8 * j);
            pl |= ((uint32_t)(uint8_t)(int8_t)lo) << (8 * j);
        }
        wh[k4] = ph; wl[k4] = pl;
    }
    size_t o = (size_t)c * R + r0 + rs;
    uint4 vh; vh.x = wh[0]; vh.y = wh[1]; vh.z = wh[2]; vh.w = wh[3];
    uint4 vl; vl.x = wl[0]; vl.y = wl[1]; vl.z = wl[2]; vl.w = wl[3];
    *(uint4*)(oh + o) = vh;
    *(uint4*)(ol + o) = vl;
    if (blockIdx.y == 0 && (tid & 7) == 0) scale[c] = m * (1.0f / 16256.0f);
}

// row-major quantize (A side), vectorized: float4 in, char4 x2 out
__global__ void quantA(const float* __restrict__ in, const unsigned* __restrict__ amaxu,
                       int8_t* __restrict__ oh, int8_t* __restrict__ ol,
                       float* __restrict__ scale) {
    int i4 = blockIdx.x * 256 + threadIdx.x;
    if (i4 >= N_NODES * HIDD / 4) return;
    int idx = i4 * 4;
    int row = idx >> 12;
    float m = __uint_as_float(amaxu[row]);
    float inv = (m > 0.0f) ? (16256.0f / m) : 0.0f;
    float4 v = *(const float4*)(in + idx);
    const float vv[4] = {v.x, v.y, v.z, v.w};
    uint32_t ph = 0, pl = 0;
    #pragma unroll
    for (int j = 0; j < 4; j++) {
        float q = rintf(vv[j] * inv);
        float h = rintf(q * (1.0f / 128.0f));
        ph |= ((uint32_t)(uint8_t)(int8_t)h) << (8 * j);
        pl |= ((uint32_t)(uint8_t)(int8_t)(q - 128.0f * h)) << (8 * j);
    }
    *(uint32_t*)(oh + idx) = ph;
    *(uint32_t*)(ol + idx) = pl;
    if ((idx & (HIDD - 1)) == 0) scale[row] = m * (1.0f / 16256.0f);
}

// ===================== IMMA GEMM: C = w @ B  (A exact s8) ==================
template<bool RELU>
__global__ __launch_bounds__(256)
void gemm_wB(const int8_t* __restrict__ A,
             const int8_t* __restrict__ Bhi, const int8_t* __restrict__ Blo,
             float* __restrict__ C, int Kb, int NC,
             const float* __restrict__ sb, const int* __restrict__ deg,
             const float* __restrict__ bias, unsigned* __restrict__ amaxU)
{
    extern __shared__ int8_t smem[];
    constexpr int SROW = 80;
    constexpr int TILE = 128 * SROW;
    constexpr int OFF_A = 0, OFF_BH = TILE, OFF_BL = 2 * TILE;
    constexpr int SS = 3 * TILE;

    const int tid = threadIdx.x;
    const int w   = tid >> 5;
    const int l   = tid & 31;
    const int wm  = w >> 2;
    const int wn  = w & 3;
    const int bm  = blockIdx.y * 128;
    const int bn  = blockIdx.x * 128;
    const uint32_t smb = smem_u32(smem);

    auto load_stage = [&](int st, int k0) {
        const uint32_t sbase = smb + (uint32_t)st * SS;
        #pragma unroll
        for (int it = 0; it < 2; it++) {
            int idx = tid + it * 256;
            int r = idx >> 2, c = idx & 3;
            uint32_t so = (uint32_t)(r * SROW + c * 16);
            cp16(sbase + OFF_A  + so, A   + (size_t)(bm + r) * Kb + k0 + c * 16);
            cp16(sbase + OFF_BH + so, Bhi + (size_t)(bn + r) * Kb + k0 + c * 16);
            cp16(sbase + OFF_BL + so, Blo + (size_t)(bn + r) * Kb + k0 + c * 16);
        }
        CP_COMMIT();
    };

    int accH[4][4][4], accL[4][4][4];
    #pragma unroll
    for (int i = 0; i < 4; i++)
        #pragma unroll
        for (int j = 0; j < 4; j++)
            #pragma unroll
            for (int e = 0; e < 4; e++) { accH[i][j][e] = 0; accL[i][j][e] = 0; }

    const int NK = Kb >> 6;
    load_stage(0, 0);
    if (NK > 1) load_stage(1, 64);

    const uint32_t a_off = (uint32_t)((wm * 64 + (l & 15)) * SROW + (l >> 4) * 16);
    const uint32_t b_off = (uint32_t)((wn * 32 + (l & 15)) * SROW + (l >> 4) * 16);

    for (int kt = 0; kt < NK; kt++) {
        if (kt == NK - 1) { CP_WAIT0(); } else { CP_WAIT1(); }
        __syncthreads();
        if (kt + 2 < NK) load_stage((kt + 2) % 3, (kt + 2) << 6);

        const uint32_t sbase = smb + (uint32_t)((kt % 3) * SS);
        #pragma unroll
        for (int ks = 0; ks < 2; ks++) {
            const uint32_t ko = (uint32_t)ks * 32;
            uint32_t a[4][4];
            #pragma unroll
            for (int mt = 0; mt < 4; mt++)
                ldmx4(a[mt], sbase + OFF_A + a_off + (uint32_t)(mt * 16 * SROW) + ko);

            uint32_t bhi[4][2], blo[4][2];
            #pragma unroll
            for (int np = 0; np < 2; np++) {
                uint32_t r[4];
                ldmx4(r, sbase + OFF_BH + b_off + (uint32_t)(np * 16 * SROW) + ko);
                bhi[np * 2][0] = r[0]; bhi[np * 2 + 1][0] = r[1];
                bhi[np * 2][1] = r[2]; bhi[np * 2 + 1][1] = r[3];
                ldmx4(r, sbase + OFF_BL + b_off + (uint32_t)(np * 16 * SROW) + ko);
                blo[np * 2][0] = r[0]; blo[np * 2 + 1][0] = r[1];
                blo[np * 2][1] = r[2]; blo[np * 2 + 1][1] = r[3];
            }

            #pragma unroll
            for (int mt = 0; mt < 4; mt++)
                #pragma unroll
                for (int nt = 0; nt < 4; nt++)
                    imma16832(accH[mt][nt], a[mt], bhi[nt]);
            #pragma unroll
            for (int mt = 0; mt < 4; mt++)
                #pragma unroll
                for (int nt = 0; nt < 4; nt++)
                    imma16832(accL[mt][nt], a[mt], blo[nt]);
        }
        __syncthreads();
    }

    #pragma unroll
    for (int mt = 0; mt < 4; mt++) {
        const int row0 = bm + wm * 64 + mt * 16 + (l >> 2);
        const float rs0 = 1.0f / (float)deg[row0];
        const float rs1 = 1.0f / (float)deg[row0 + 8];
        float rm0 = 0.0f, rm1 = 0.0f;
        #pragma unroll
        for (int nt = 0; nt < 4; nt++) {
            const int col = bn + wn * 32 + nt * 8 + (l & 3) * 2;
            const float sb0 = sb[col], sb1 = sb[col + 1];
            const float bb0 = bias[col], bb1 = bias[col + 1];
            int c0 = accH[mt][nt][0] * 128 + accL[mt][nt][0];
            int c1 = accH[mt][nt][1] * 128 + accL[mt][nt][1];
            int c2 = accH[mt][nt][2] * 128 + accL[mt][nt][2];
            int c3 = accH[mt][nt][3] * 128 + accL[mt][nt][3];
            float v0 = (float)c0 * sb0 * rs0 + bb0;
            float v1 = (float)c1 * sb1 * rs0 + bb1;
            float v2 = (float)c2 * sb0 * rs1 + bb0;
            float v3 = (float)c3 * sb1 * rs1 + bb1;
            if (RELU) {
                v0 = fmaxf(v0, 0.0f); v1 = fmaxf(v1, 0.0f);
                v2 = fmaxf(v2, 0.0f); v3 = fmaxf(v3, 0.0f);
            }
            rm0 = fmaxf(rm0, fmaxf(fabsf(v0), fabsf(v1)));
            rm1 = fmaxf(rm1, fmaxf(fabsf(v2), fabsf(v3)));
            *(float2*)(C + (size_t)row0 * NC + col)       = make_float2(v0, v1);
            *(float2*)(C + (size_t)(row0 + 8) * NC + col) = make_float2(v2, v3);
        }
        if (amaxU) {
            atomicMax(amaxU + row0,     __float_as_uint(rm0));
            atomicMax(amaxU + row0 + 8, __float_as_uint(rm1));
        }
    }
}

// ===================== IMMA GEMM: C = A @ B^T (both split, 3 terms) ========
__global__ __launch_bounds__(256)
void gemm_AB(const int8_t* __restrict__ Ahi, const int8_t* __restrict__ Alo,
             const int8_t* __restrict__ Bhi, const int8_t* __restrict__ Blo,
             float* __restrict__ C, int Kb, int NC,
             const float* __restrict__ sa, const float* __restrict__ sbv,
             unsigned* __restrict__ cmaxU)
{
    extern __shared__ int8_t smem[];
    constexpr int SROW = 80;
    constexpr int TILE = 128 * SROW;
    constexpr int OFF_AH = 0, OFF_AL = TILE, OFF_BH = 2 * TILE, OFF_BL = 3 * TILE;
    constexpr int SS = 4 * TILE;

    const int tid = threadIdx.x;
    const int w   = tid >> 5;
    const int l   = tid & 31;
    const int wm  = w >> 2;
    const int wn  = w & 3;
    const int bm  = blockIdx.y * 128;
    const int bn  = blockIdx.x * 128;
    const uint32_t smb = smem_u32(smem);

    auto load_stage = [&](int st, int k0) {
        const uint32_t sbase = smb + (uint32_t)st * SS;
        #pragma unroll
        for (int it = 0; it < 2; it++) {
            int idx = tid + it * 256;
            int r = idx >> 2, c = idx & 3;
            uint32_t so = (uint32_t)(r * SROW + c * 16);
            cp16(sbase + OFF_AH + so, Ahi + (size_t)(bm + r) * Kb + k0 + c * 16);
            cp16(sbase + OFF_AL + so, Alo + (size_t)(bm + r) * Kb + k0 + c * 16);
            cp16(sbase + OFF_BH + so, Bhi + (size_t)(bn + r) * Kb + k0 + c * 16);
            cp16(sbase + OFF_BL + so, Blo + (size_t)(bn + r) * Kb + k0 + c * 16);
        }
        CP_COMMIT();
    };

    int accHH[4][4][4], accM[4][4][4];
    #pragma unroll
    for (int i = 0; i < 4; i++)
        #pragma unroll
        for (int j = 0; j < 4; j++)
            #pragma unroll
            for (int e = 0; e < 4; e++) { accHH[i][j][e] = 0; accM[i][j][e] = 0; }

    const int NK = Kb >> 6;
    load_stage(0, 0);
    if (NK > 1) load_stage(1, 64);

    const uint32_t a_off = (uint32_t)((wm * 64 + (l & 15)) * SROW + (l >> 4) * 16);
    const uint32_t b_off = (uint32_t)((wn * 32 + (l & 15)) * SROW + (l >> 4) * 16);

    for (int kt = 0; kt < NK; kt++) {
        if (kt == NK - 1) { CP_WAIT0(); } else { CP_WAIT1(); }
        __syncthreads();
        if (kt + 2 < NK) load_stage((kt + 2) % 3, (kt + 2) << 6);

        const uint32_t sbase = smb + (uint32_t)((kt % 3) * SS);
        #pragma unroll
        for (int ks = 0; ks < 2; ks++) {
            const uint32_t ko = (uint32_t)ks * 32;
            uint32_t ahi[4][4];
            #pragma unroll
            for (int mt = 0; mt < 4; mt++)
                ldmx4(ahi[mt], sbase + OFF_AH + a_off + (uint32_t)(mt * 16 * SROW) + ko);

            uint32_t bhi[4][2], blo[4][2];
            #pragma unroll
            for (int np = 0; np < 2; np++) {
                uint32_t r[4];
                ldmx4(r, sbase + OFF_BH + b_off + (uint32_t)(np * 16 * SROW) + ko);
                bhi[np * 2][0] = r[0]; bhi[np * 2 + 1][0] = r[1];
                bhi[np * 2][1] = r[2]; bhi[np * 2 + 1][1] = r[3];
                ldmx4(r, sbase + OFF_BL + b_off + (uint32_t)(np * 16 * SROW) + ko);
                blo[np * 2][0] = r[0]; blo[np * 2 + 1][0] = r[1];
                blo[np * 2][1] = r[2]; blo[np * 2 + 1][1] = r[3];
            }

            #pragma unroll
            for (int mt = 0; mt < 4; mt++)
                #pragma unroll
                for (int nt = 0; nt < 4; nt++)
                    imma16832(accHH[mt][nt], ahi[mt], bhi[nt]);
            #pragma unroll
            for (int mt = 0; mt < 4; mt++)
                #pragma unroll
                for (int nt = 0; nt < 4; nt++)
                    imma16832(accM[mt][nt], ahi[mt], blo[nt]);

            uint32_t alo[4][4];
            #pragma unroll
            for (int mt = 0; mt < 4; mt++)
                ldmx4(alo[mt], sbase + OFF_AL + a_off + (uint32_t)(mt * 16 * SROW) + ko);
            #pragma unroll
            for (int mt = 0; mt < 4; mt++)
                #pragma unroll
                for (int nt = 0; nt < 4; nt++)
                    imma16832(accM[mt][nt], alo[mt], bhi[nt]);
        }
        __syncthreads();
    }

    float cm[8];
    #pragma unroll
    for (int i = 0; i < 8; i++) cm[i] = 0.0f;

    #pragma unroll
    for (int mt = 0; mt < 4; mt++) {
        const int row0 = bm + wm * 64 + mt * 16 + (l >> 2);
        const float sa0 = sa[row0], sa1 = sa[row0 + 8];
        #pragma unroll
        for (int nt = 0; nt < 4; nt++) {
            const int col = bn + wn * 32 + nt * 8 + (l & 3) * 2;
            const float sb0 = sbv[col], sb1 = sbv[col + 1];
            float v0 = sa0 * sb0 * (16384.0f * (float)accHH[mt][nt][0] + 128.0f * (float)accM[mt][nt][0]);
            float v1 = sa0 * sb1 * (16384.0f * (float)accHH[mt][nt][1] + 128.0f * (float)accM[mt][nt][1]);
            float v2 = sa1 * sb0 * (16384.0f * (float)accHH[mt][nt][2] + 128.0f * (float)accM[mt][nt][2]);
            float v3 = sa1 * sb1 * (16384.0f * (float)accHH[mt][nt][3] + 128.0f * (float)accM[mt][nt][3]);
            cm[nt * 2]     = fmaxf(cm[nt * 2],     fmaxf(fabsf(v0), fabsf(v2)));
            cm[nt * 2 + 1] = fmaxf(cm[nt * 2 + 1], fmaxf(fabsf(v1), fabsf(v3)));
            *(float2*)(C + (size_t)row0 * NC + col)       = make_float2(v0, v1);
            *(float2*)(C + (size_t)(row0 + 8) * NC + col) = make_float2(v2, v3);
        }
    }
    if (cmaxU) {
        #pragma unroll
        for (int nt = 0; nt < 4; nt++) {
            const int col = bn + wn * 32 + nt * 8 + (l & 3) * 2;
            atomicMax(cmaxU + col,     __float_as_uint(cm[nt * 2]));
            atomicMax(cmaxU + col + 1, __float_as_uint(cm[nt * 2 + 1]));
        }
    }
}

// ===================== split-K FFMA sgemm (gc3, BK=32 coalesced) ===========
template<int V>
__device__ __forceinline__ void ldvec(float* d, const float* s) {
    if constexpr (V == 4) {
        *(float4*)d = *(const float4*)s;
    } else if constexpr (V == 2) {
        *(float2*)d = *(const float2*)s;
    } else {
        #pragma unroll
        for (int i = 0; i < V; i++) d[i] = s[i];
    }
}

template<int BM, int BN, int BK, int TM, int TN>
__global__ __launch_bounds__(256)
void sgemm_sk(const float* __restrict__ A, const float* __restrict__ B,
              float* __restrict__ C, int M, int N, int K, int lda)
{
    static_assert((BM / TM) * (BN / TN) == 256, "need 256 threads");
    constexpr int ALOAD = BM * BK / 256;
    constexpr int BLOAD = BK * BN / 256;

    __shared__ float As[2][BK * BM];
    __shared__ float Bs[2][BK * BN];

    const int s = blockIdx.z;
    A += (size_t)s * K;
    B += (size_t)s * K * N;
    C += (size_t)s * M * N;

    const int tid = threadIdx.x;
    const int bm  = blockIdx.y * BM;
    const int bn  = blockIdx.x * BN;
    const int tx  = tid % (BN / TN);
    const int ty  = tid / (BN / TN);

    #pragma unroll
    for (int l = 0; l < ALOAD; l++) {
        int idx = tid + l * 256;
        int r = idx / BK, c = idx % BK;
        As[0][c * BM + r] = A[(size_t)(bm + r) * lda + c];
    }
    #pragma unroll
    for (int l = 0; l < BLOAD; l++) {
        int idx = tid + l * 256;
        int r = idx / BN, c = idx % BN;
        Bs[0][r * BN + c] = B[(size_t)r * N + bn + c];
    }
    __syncthreads();

    float acc[TM * TN];
    #pragma unroll
    for (int i = 0; i < TM * TN; i++) acc[i] = 0.0f;

    float areg[ALOAD], breg[BLOAD];
    const int nk = K / BK;
    int st = 0;

    for (int kt = 0; kt < nk; kt++) {
        if (kt + 1 < nk) {
            const int k0 = (kt + 1) * BK;
            #pragma unroll
            for (int l = 0; l < ALOAD; l++) {
                int idx = tid + l * 256;
                int r = idx / BK, c = idx % BK;
                areg[l] = A[(size_t)(bm + r) * lda + k0 + c];
            }
            #pragma unroll
            for (int l = 0; l < BLOAD; l++) {
                int idx = tid + l * 256;
                int r = idx / BN, c = idx % BN;
                breg[l] = B[(size_t)(k0 + r) * N + bn + c];
            }
        }
        #pragma unroll
        for (int kk = 0; kk < BK; kk++) {
            float fa[TM], fb[TN];
            ldvec<TM>(fa, &As[st][kk * BM + ty * TM]);
            ldvec<TN>(fb, &Bs[st][kk * BN + tx * TN]);
            #pragma unroll
            for (int i = 0; i < TM; i++)
                #pragma unroll
                for (int j = 0; j < TN; j++)
                    acc[i * TN + j] += fa[i] * fb[j];
        }
        if (kt + 1 < nk) {
            st ^= 1;
            #pragma unroll
            for (int l = 0; l < ALOAD; l++) {
                int idx = tid + l * 256;
                int r = idx / BK, c = idx % BK;
                As[st][c * BM + r] = areg[l];
            }
            #pragma unroll
            for (int l = 0; l < BLOAD; l++) {
                int idx = tid + l * 256;
                int r = idx / BN, c = idx % BN;
                Bs[st][r * BN + c] = breg[l];
            }
            __syncthreads();
        }
    }

    const int row0 = bm + ty * TM;
    const int col0 = bn + tx * TN;
    #pragma unroll
    for (int i = 0; i < TM; i++)
        #pragma unroll
        for (int j = 0; j < TN; j++)
            C[(size_t)(row0 + i) * N + col0 + j] = acc[i * TN + j];
}

template<int MODE>
__global__ void sk_reduce(const float* __restrict__ part, int M, int S,
                          float* __restrict__ C, float* __restrict__ C2,
                          const int* __restrict__ deg, const float* __restrict__ bias) {
    int i = blockIdx.x * 256 + threadIdx.x;
    if (i >= M * CODE) return;
    int m = i >> 6, c = i & 63;
    float v = 0.0f;
    for (int s = 0; s < S; s++) v += part[(size_t)s * M * CODE + i];
    if (MODE == 3) {
        v = v * (1.0f / (float)deg[m]) + bias[c];
        C[i] = v;
        C2[i] = tanhf(v);
    } else {
        C[i] = v;
    }
}

// ===================== launch ==============================================
extern "C" void kernel_launch(void* const* d_in, const int* in_sizes, int n_in,
                              void* d_out, int out_size) {
    const float* x  = (const float*)d_in[0];
    const float* W1 = (const float*)d_in[1];
    const float* b1 = (const float*)d_in[2];
    const float* W2 = (const float*)d_in[3];
    const float* b2 = (const float*)d_in[4];
    const float* W3 = (const float*)d_in[5];
    const float* b3 = (const float*)d_in[6];

    void* p;
    float *w, *P, *F1, *P3, *part, *sb1, *sb2, *sw, *sa;
    int8_t *x8, *w8, *BThi, *BTlo, *Ahi, *Alo, *W2Thi, *W2Tlo;
    unsigned *mxP1, *mxP2, *mxW, *amaxU;
    int* deg;
    cudaGetSymbolAddress(&p, g_x8);    x8    = (int8_t*)p;
    cudaGetSymbolAddress(&p, g_w);     w     = (float*)p;
    cudaGetSymbolAddress(&p, g_w8);    w8    = (int8_t*)p;
    cudaGetSymbolAddress(&p, g_deg);   deg   = (int*)p;
    cudaGetSymbolAddress(&p, g_P);     P     = (float*)p;
    cudaGetSymbolAddress(&p, g_F1);    F1    = (float*)p;
    cudaGetSymbolAddress(&p, g_P3);    P3    = (float*)p;
    cudaGetSymbolAddress(&p, g_part);  part  = (float*)p;
    cudaGetSymbolAddress(&p, g_BThi);  BThi  = (int8_t*)p;
    cudaGetSymbolAddress(&p, g_BTlo);  BTlo  = (int8_t*)p;
    cudaGetSymbolAddress(&p, g_Ahi);   Ahi   = (int8_t*)p;
    cudaGetSymbolAddress(&p, g_Alo);   Alo   = (int8_t*)p;
    cudaGetSymbolAddress(&p, g_W2Thi); W2Thi = (int8_t*)p;
    cudaGetSymbolAddress(&p, g_W2Tlo); W2Tlo = (int8_t*)p;
    cudaGetSymbolAddress(&p, g_mxP1);  mxP1  = (unsigned*)p;
    cudaGetSymbolAddress(&p, g_mxP2);  mxP2  = (unsigned*)p;
    cudaGetSymbolAddress(&p, g_mxW);   mxW   = (unsigned*)p;
    cudaGetSymbolAddress(&p, g_sb1);   sb1   = (float*)p;
    cudaGetSymbolAddress(&p, g_sb2);   sb2   = (float*)p;
    cudaGetSymbolAddress(&p, g_sw);    sw    = (float*)p;
    cudaGetSymbolAddress(&p, g_sa);    sa    = (float*)p;
    cudaGetSymbolAddress(&p, g_amax);  amaxU = (unsigned*)p;

    float* featOut = (float*)d_out;
    float* hidOut  = featOut + (size_t)N_NODES * HIDD;
    float* codeOut = hidOut  + (size_t)N_NODES * CODE;

    constexpr int SMEM_ADJ = 2 * 2 * 128 * 80;  // 40960
    constexpr int SMEM_WB  = 3 * 3 * 128 * 80;  // 92160
    constexpr int SMEM_AB  = 3 * 4 * 128 * 80;  // 122880
    cudaFuncSetAttribute(gemm_adj,       cudaFuncAttributeMaxDynamicSharedMemorySize, SMEM_ADJ);
    cudaFuncSetAttribute(gemm_wB<false>, cudaFuncAttributeMaxDynamicSharedMemorySize, SMEM_WB);
    cudaFuncSetAttribute(gemm_wB<true>,  cudaFuncAttributeMaxDynamicSharedMemorySize, SMEM_WB);
    cudaFuncSetAttribute(gemm_AB,        cudaFuncAttributeMaxDynamicSharedMemorySize, SMEM_AB);

    // fused prep + adjacency (exact IMMA)
    prep_all<<<(N_NODES * KPAD + 255) / 256, 256>>>(x);
    gemm_adj<<<dim3(N_NODES / 128, N_NODES / 128), 256, SMEM_ADJ>>>(x8, w, w8, deg);

    // W2 quantization
    colmax<<<dim3(HIDD / 256, 16), 256>>>(W2, HIDD, HIDD, mxW);
    quantT<<<dim3(HIDD / 32, HIDD / 128), 256>>>(W2, HIDD, HIDD, mxW, W2Thi, W2Tlo, sw);

    // gc1: P1 = x@W1 (fused colmax) ; quantize P1^T ; feat1 = (w@P1)/deg+b1 (fused rowmax)
    xw1_kernel<<<N_NODES, 256>>>(W1);
    quantT<<<dim3(HIDD / 32, N_NODES / 128), 256>>>(P, N_NODES, HIDD, mxP1, BThi, BTlo, sb1);
    gemm_wB<false><<<dim3(HIDD / 128, N_NODES / 128), 256, SMEM_WB>>>(
        w8, BThi, BTlo, F1, N_NODES, HIDD, sb1, deg, b1, amaxU);

    // gc2: quantize feat1 rows ; P2 = f1q@W2q (fused colmax) ; quantize P2^T ;
    //      feat = relu((w@P2)/deg+b2) -> d_out
    quantA<<<(N_NODES * HIDD / 4 + 255) / 256, 256>>>(F1, amaxU, Ahi, Alo, sa);
    gemm_AB<<<dim3(HIDD / 128, N_NODES / 128), 256, SMEM_AB>>>(
        Ahi, Alo, W2Thi, W2Tlo, P, HIDD, HIDD, sa, sw, mxP2);
    quantT<<<dim3(HIDD / 32, N_NODES / 128), 256>>>(P, N_NODES, HIDD, mxP2, BThi, BTlo, sb2);
    gemm_wB<true><<<dim3(HIDD / 128, N_NODES / 128), 256, SMEM_WB>>>(
        w8, BThi, BTlo, featOut, N_NODES, HIDD, sb2, deg, b2, nullptr);

    // gc3 (fp32 split-K)
    sgemm_sk<64, 64, 32, 4, 4><<<dim3(1, N_NODES / 64, 8), 256>>>(
        featOut, W3, part, N_NODES, CODE, HIDD / 8, HIDD);
    sk_reduce<0><<<(N_NODES * CODE + 255) / 256, 256>>>(
        part, N_NODES, 8, P3, nullptr, nullptr, nullptr);
    sgemm_sk<64, 64, 32, 4, 4><<<dim3(1, N_NODES / 64, 8), 256>>>(
        w, P3, part, N_NODES, CODE, N_NODES / 8, N_NODES);
    sk_reduce<3><<<(N_NODES * CODE + 255) / 256, 256>>>(
        part, N_NODES, 8, hidOut, codeOut, deg, b3);
}

// round 15
// speedup vs baseline: 1.1846x; 1.1303x over previous
#include <cuda_runtime.h>
#include <cuda_bf16.h>
#include <math.h>
#include <stdint.h>

#define N_NODES 2048
#define TXT     1386
#define HIDD    4096
#define CODE    64
#define XWORDS  44    // ceil(1386/32)
#define KPAD    1408  // 1386 padded to 64

// ===================== device scratch (no allocation allowed) ===============
__device__ __align__(16) unsigned g_xb[N_NODES * XWORDS];
__device__ __align__(16) int8_t   g_x8[(size_t)N_NODES * KPAD];      // x as s8 0/1
__device__ __align__(16) float    g_w [(size_t)N_NODES * N_NODES];   // fp32 adj (gc3)
__device__ __align__(16) int8_t   g_w8[(size_t)N_NODES * N_NODES];   // s8 adj (exact)
__device__ int                    g_deg[N_NODES];
__device__ __align__(16) float    g_P  [(size_t)N_NODES * HIDD];     // P1 / P2 fp32
__device__ __align__(16) float    g_F1 [(size_t)N_NODES * HIDD];     // feat1 fp32
__device__ __align__(16) int8_t   g_BThi[(size_t)HIDD * N_NODES];
__device__ __align__(16) int8_t   g_BTlo[(size_t)HIDD * N_NODES];
__device__ __align__(16) int8_t   g_Ahi[(size_t)N_NODES * HIDD];
__device__ __align__(16) int8_t   g_Alo[(size_t)N_NODES * HIDD];
__device__ __align__(16) int8_t   g_W2Thi[(size_t)HIDD * HIDD];
__device__ __align__(16) int8_t   g_W2Tlo[(size_t)HIDD * HIDD];
__device__ unsigned               g_mxP1[HIDD];
__device__ unsigned               g_mxP2[HIDD];
__device__ unsigned               g_mxW [HIDD];
__device__ float                  g_sb1[HIDD], g_sb2[HIDD], g_sw[HIDD];
__device__ float                  g_sa[N_NODES];
__device__ unsigned               g_amax[N_NODES];
__device__ float                  g_P3[(size_t)N_NODES * CODE];
__device__ float                  g_part[8 * (size_t)N_NODES * CODE];

// ===================== PTX helpers =========================================
__device__ __forceinline__ uint32_t smem_u32(const void* p) {
    uint32_t a;
    asm("{ .reg .u64 t; cvta.to.shared.u64 t, %1; cvt.u32.u64 %0, t; }" : "=r"(a) : "l"(p));
    return a;
}
__device__ __forceinline__ void cp16(uint32_t s, const void* g) {
    asm volatile("cp.async.cg.shared.global [%0], [%1], 16;"
        :: "r"(s), "l"(__cvta_generic_to_global(g)) : "memory");
}
#define CP_COMMIT() asm volatile("cp.async.commit_group;" ::: "memory")
#define CP_WAIT1()  asm volatile("cp.async.wait_group 1;" ::: "memory")
#define CP_WAIT0()  asm volatile("cp.async.wait_group 0;" ::: "memory")

__device__ __forceinline__ void ldmx4(uint32_t* r, uint32_t addr) {
    asm volatile("ldmatrix.sync.aligned.m8n8.x4.shared.b16 {%0,%1,%2,%3}, [%4];"
        : "=r"(r[0]), "=r"(r[1]), "=r"(r[2]), "=r"(r[3]) : "r"(addr));
}
__device__ __forceinline__ void imma16832(int* c, const uint32_t* a, const uint32_t* b) {
    asm volatile("mma.sync.aligned.m16n8k32.row.col.s32.s8.s8.s32 "
        "{%0,%1,%2,%3}, {%4,%5,%6,%7}, {%8,%9}, {%0,%1,%2,%3};"
        : "+r"(c[0]), "+r"(c[1]), "+r"(c[2]), "+r"(c[3])
        : "r"(a[0]), "r"(a[1]), "r"(a[2]), "r"(a[3]), "r"(b[0]), "r"(b[1]));
}

// ===================== fused prep: init + bitpack + s8 pack ================
__global__ void prep_all(const float* __restrict__ x) {
    int idx = blockIdx.x * 256 + threadIdx.x;
    if (idx < HIDD) { g_mxP1[idx] = 0; g_mxP2[idx] = 0; g_mxW[idx] = 0; }
    if (idx < N_NODES) { g_deg[idx] = 0; g_amax[idx] = 0; }
    if (idx < N_NODES * XWORDS) {
        int row = idx / XWORDS, w = idx - row * XWORDS;
        unsigned bits = 0;
        int base = w * 32;
        #pragma unroll 8
        for (int b = 0; b < 32; b++) {
            int c = base + b;
            if (c < TXT && x[(size_t)row * TXT + c] != 0.0f) bits |= (1u << b);
        }
        g_xb[idx] = bits;
    }
    if (idx < N_NODES * KPAD) {
        int row = idx / KPAD, col = idx - row * KPAD;
        int8_t v = 0;
        if (col < TXT && x[(size_t)row * TXT + col] != 0.0f) v = 1;
        g_x8[idx] = v;
    }
}

// ============ adjacency via exact int8 IMMA: S = x8 @ x8^T ================
__global__ __launch_bounds__(256, 2)
void gemm_adj(const int8_t* __restrict__ X, float* __restrict__ Wf,
              int8_t* __restrict__ W8, int* __restrict__ deg)
{
    extern __shared__ int8_t smem[];
    constexpr int SROW = 80;
    constexpr int TILE = 128 * SROW;
    constexpr int OFF_A = 0, OFF_B = TILE;
    constexpr int SS = 2 * TILE;

    const int tid = threadIdx.x;
    const int w   = tid >> 5;
    const int l   = tid & 31;
    const int wm  = w >> 2;
    const int wn  = w & 3;
    const int bm  = blockIdx.y * 128;
    const int bn  = blockIdx.x * 128;
    const uint32_t smb = smem_u32(smem);

    auto load_stage = [&](int st, int k0) {
        const uint32_t sbase = smb + (uint32_t)st * SS;
        #pragma unroll
        for (int it = 0; it < 2; it++) {
            int idx = tid + it * 256;
            int r = idx >> 2, c = idx & 3;
            uint32_t so = (uint32_t)(r * SROW + c * 16);
            cp16(sbase + OFF_A + so, X + (size_t)(bm + r) * KPAD + k0 + c * 16);
            cp16(sbase + OFF_B + so, X + (size_t)(bn + r) * KPAD + k0 + c * 16);
        }
        CP_COMMIT();
    };

    int acc[4][4][4];
    #pragma unroll
    for (int i = 0; i < 4; i++)
        #pragma unroll
        for (int j = 0; j < 4; j++)
            #pragma unroll
            for (int e = 0; e < 4; e++) acc[i][j][e] = 0;

    const int NK = KPAD >> 6;   // 22
    load_stage(0, 0);
    load_stage(1, 64);

    const uint32_t a_off = (uint32_t)((wm * 64 + (l & 15)) * SROW + (l >> 4) * 16);
    const uint32_t b_off = (uint32_t)((wn * 32 + (l & 15)) * SROW + (l >> 4) * 16);

    for (int kt = 0; kt < NK; kt++) {
        if (kt >= NK - 1) { CP_WAIT0(); } else { CP_WAIT1(); }
        __syncthreads();

        const uint32_t sbase = smb + (uint32_t)((kt & 1) * SS);
        #pragma unroll
        for (int ks = 0; ks < 2; ks++) {
            const uint32_t ko = (uint32_t)ks * 32;
            uint32_t a[4][4];
            #pragma unroll
            for (int mt = 0; mt < 4; mt++)
                ldmx4(a[mt], sbase + OFF_A + a_off + (uint32_t)(mt * 16 * SROW) + ko);
            uint32_t b[4][2];
            #pragma unroll
            for (int np = 0; np < 2; np++) {
                uint32_t r[4];
                ldmx4(r, sbase + OFF_B + b_off + (uint32_t)(np * 16 * SROW) + ko);
                b[np * 2][0] = r[0]; b[np * 2 + 1][0] = r[1];
                b[np * 2][1] = r[2]; b[np * 2 + 1][1] = r[3];
            }
            #pragma unroll
            for (int mt = 0; mt < 4; mt++)
                #pragma unroll
                for (int nt = 0; nt < 4; nt++)
                    imma16832(acc[mt][nt], a[mt], b[nt]);
        }
        __syncthreads();
        if (kt + 2 < NK) load_stage(kt & 1, (kt + 2) << 6);
    }

    #pragma unroll
    for (int mt = 0; mt < 4; mt++) {
        const int row0 = bm + wm * 64 + mt * 16 + (l >> 2);
        const int row1 = row0 + 8;
        int d0 = 0, d1 = 0;
        #pragma unroll
        for (int nt = 0; nt < 4; nt++) {
            const int col = bn + wn * 32 + nt * 8 + (l & 3) * 2;
            int w0 = (acc[mt][nt][0] > 0) + (row0 == col);
            int w1 = (acc[mt][nt][1] > 0) + (row0 == col + 1);
            int w2 = (acc[mt][nt][2] > 0) + (row1 == col);
            int w3 = (acc[mt][nt][3] > 0) + (row1 == col + 1);
            *(float2*)(Wf + (size_t)row0 * N_NODES + col) = make_float2((float)w0, (float)w1);
            *(float2*)(Wf + (size_t)row1 * N_NODES + col) = make_float2((float)w2, (float)w3);
            char2 c01; c01.x = (char)w0; c01.y = (char)w1;
            char2 c23; c23.x = (char)w2; c23.y = (char)w3;
            *(char2*)(W8 + (size_t)row0 * N_NODES + col) = c01;
            *(char2*)(W8 + (size_t)row1 * N_NODES + col) = c23;
            d0 += w0 + w1;
            d1 += w2 + w3;
        }
        atomicAdd(&deg[row0], d0);
        atomicAdd(&deg[row1], d1);
    }
}

// ===================== xw1 + fused column-max ==============================
__global__ void xw1_kernel(const float* __restrict__ W1) {
    __shared__ int idxs[1392];
    __shared__ int nidx;
    const int row = blockIdx.x;
    const int tid = threadIdx.x;
    if (tid == 0) {
        int n = 0;
        #pragma unroll 4
        for (int w = 0; w < XWORDS; w++) {
            unsigned b = g_xb[row * XWORDS + w];
            while (b) { int bit = __ffs(b) - 1; idxs[n++] = w * 32 + bit; b &= b - 1; }
        }
        nidx = n;
    }
    __syncthreads();

    float acc[16];
    #pragma unroll
    for (int j = 0; j < 16; j++) acc[j] = 0.0f;
    const int n = nidx;
    for (int t = 0; t < n; t++) {
        const float* wr = W1 + (size_t)idxs[t] * HIDD + tid;
        #pragma unroll
        for (int j = 0; j < 16; j++) acc[j] += wr[j * 256];
    }
    float* out = g_P + (size_t)row * HIDD + tid;
    #pragma unroll
    for (int j = 0; j < 16; j++) {
        out[j * 256] = acc[j];
        atomicMax(&g_mxP1[tid + j * 256], __float_as_uint(fabsf(acc[j])));
    }
}

// column abs-max (standalone, for W2 only)
__global__ void colmax(const float* __restrict__ in, int R, int C, unsigned* __restrict__ mx) {
    int col = blockIdx.x * 256 + threadIdx.x;
    if (col >= C) return;
    int rchunk = R / gridDim.y;
    int r0 = blockIdx.y * rchunk;
    float m = 0.0f;
    for (int r = r0; r < r0 + rchunk; r++)
        m = fmaxf(m, fabsf(in[(size_t)r * C + col]));
    atomicMax(mx + col, __float_as_uint(m));
}

// transpose + 15-bit split quantize, coalesced stores (32c x 128r tiles)
__global__ void quantT(const float* __restrict__ in, int R, int C,
                       const unsigned* __restrict__ mxu,
                       int8_t* __restrict__ oh, int8_t* __restrict__ ol,
                       float* __restrict__ scale) {
    __shared__ float t[32][129];
    const int c0 = blockIdx.x * 32, r0 = blockIdx.y * 128;
    const int tid = threadIdx.x;
    #pragma unroll
    for (int i = 0; i < 16; i++) {
        int e = tid + i * 256;
        int r = e >> 5, c = e & 31;
        t[c][r] = in[(size_t)(r0 + r) * C + c0 + c];
    }
    __syncthreads();

    const int cc = tid >> 3;
    const int rs = (tid & 7) * 16;
    const int c  = c0 + cc;
    const float m = __uint_as_float(mxu[c]);
    const float inv = (m > 0.0f) ? (16256.0f / m) : 0.0f;

    uint32_t wh[4], wl[4];
    #pragma unroll
    for (int k4 = 0; k4 < 4; k4++) {
        uint32_t ph = 0, pl = 0;
        #pragma unroll
        for (int j = 0; j < 4; j++) {
            float q = rintf(t[cc][rs + k4 * 4 + j] * inv);
            float h = rintf(q * (1.0f / 128.0f));
            float lo = q - 128.0f * h;
            ph |= ((uint32_t)(uint8_t)(int8_t)h) << (8 * j);
            pl |= ((uint32_t)(uint8_t)(int8_t)lo) << (8 * j);
        }
        wh[k4] = ph; wl[k4] = pl;
    }
    size_t o = (size_t)c * R + r0 + rs;
    uint4 vh; vh.x = wh[0]; vh.y = wh[1]; vh.z = wh[2]; vh.w = wh[3];
    uint4 vl; vl.x = wl[0]; vl.y = wl[1]; vl.z = wl[2]; vl.w = wl[3];
    *(uint4*)(oh + o) = vh;
    *(uint4*)(ol + o) = vl;
    if (blockIdx.y == 0 && (tid & 7) == 0) scale[c] = m * (1.0f / 16256.0f);
}

// row-major quantize (A side), vectorized
__global__ void quantA(const float* __restrict__ in, const unsigned* __restrict__ amaxu,
                       int8_t* __restrict__ oh, int8_t* __restrict__ ol,
                       float* __restrict__ scale) {
    int i4 = blockIdx.x * 256 + threadIdx.x;
    if (i4 >= N_NODES * HIDD / 4) return;
    int idx = i4 * 4;
    int row = idx >> 12;
    float m = __uint_as_float(amaxu[row]);
    float inv = (m > 0.0f) ? (16256.0f / m) : 0.0f;
    float4 v = *(const float4*)(in + idx);
    const float vv[4] = {v.x, v.y, v.z, v.w};
    uint32_t ph = 0, pl = 0;
    #pragma unroll
    for (int j = 0; j < 4; j++) {
        float q = rintf(vv[j] * inv);
        float h = rintf(q * (1.0f / 128.0f));
        ph |= ((uint32_t)(uint8_t)(int8_t)h) << (8 * j);
        pl |= ((uint32_t)(uint8_t)(int8_t)(q - 128.0f * h)) << (8 * j);
    }
    *(uint32_t*)(oh + idx) = ph;
    *(uint32_t*)(ol + idx) = pl;
    if ((idx & (HIDD - 1)) == 0) scale[row] = m * (1.0f / 16256.0f);
}

// ===================== IMMA GEMM: C = w @ B  -- 128x64 tiles, 2 CTAs/SM ====
// 8 warps of 32x32 (wm=w>>1 row group, wn=w&1 col group).
template<bool RELU>
__global__ __launch_bounds__(256, 2)
void gemm_wB(const int8_t* __restrict__ A,
             const int8_t* __restrict__ Bhi, const int8_t* __restrict__ Blo,
             float* __restrict__ C, int Kb, int NC,
             const float* __restrict__ sb, const int* __restrict__ deg,
             const float* __restrict__ bias, unsigned* __restrict__ amaxU)
{
    extern __shared__ int8_t smem[];
    constexpr int SROW = 80;
    constexpr int ATILE = 128 * SROW;          // 10240
    constexpr int BTILE = 64 * SROW;           // 5120
    constexpr int OFF_A = 0, OFF_BH = ATILE, OFF_BL = ATILE + BTILE;
    constexpr int SS = ATILE + 2 * BTILE;      // 20480; x3 stages = 61440

    const int tid = threadIdx.x;
    const int w   = tid >> 5;
    const int l   = tid & 31;
    const int wm  = w >> 1;                    // 0..3 (32-row group)
    const int wn  = w & 1;                     // 0..1 (32-col group)
    const int bm  = blockIdx.y * 128;
    const int bn  = blockIdx.x * 64;
    const uint32_t smb = smem_u32(smem);

    auto load_stage = [&](int st, int k0) {
        const uint32_t sbase = smb + (uint32_t)st * SS;
        #pragma unroll
        for (int it = 0; it < 2; it++) {       // A: 128 rows
            int idx = tid + it * 256;
            int r = idx >> 2, c = idx & 3;
            cp16(sbase + OFF_A + (uint32_t)(r * SROW + c * 16),
                 A + (size_t)(bm + r) * Kb + k0 + c * 16);
        }
        {                                      // BH + BL: 64 rows each
            int r = tid >> 2, c = tid & 3;
            uint32_t so = (uint32_t)(r * SROW + c * 16);
            cp16(sbase + OFF_BH + so, Bhi + (size_t)(bn + r) * Kb + k0 + c * 16);
            cp16(sbase + OFF_BL + so, Blo + (size_t)(bn + r) * Kb + k0 + c * 16);
        }
        CP_COMMIT();
    };

    int accH[2][4][4], accL[2][4][4];
    #pragma unroll
    for (int i = 0; i < 2; i++)
        #pragma unroll
        for (int j = 0; j < 4; j++)
            #pragma unroll
            for (int e = 0; e < 4; e++) { accH[i][j][e] = 0; accL[i][j][e] = 0; }

    const int NK = Kb >> 6;
    load_stage(0, 0);
    if (NK > 1) load_stage(1, 64);

    const uint32_t a_off = (uint32_t)((wm * 32 + (l & 15)) * SROW + (l >> 4) * 16);
    const uint32_t b_off = (uint32_t)((wn * 32 + (l & 15)) * SROW + (l >> 4) * 16);

    for (int kt = 0; kt < NK; kt++) {
        if (kt == NK - 1) { CP_WAIT0(); } else { CP_WAIT1(); }
        __syncthreads();
        if (kt + 2 < NK) load_stage((kt + 2) % 3, (kt + 2) << 6);

        const uint32_t sbase = smb + (uint32_t)((kt % 3) * SS);
        #pragma unroll
        for (int ks = 0; ks < 2; ks++) {
            const uint32_t ko = (uint32_t)ks * 32;
            uint32_t a[2][4];
            #pragma unroll
            for (int mt = 0; mt < 2; mt++)
                ldmx4(a[mt], sbase + OFF_A + a_off + (uint32_t)(mt * 16 * SROW) + ko);

            uint32_t bhi[4][2], blo[4][2];
            #pragma unroll
            for (int np = 0; np < 2; np++) {
                uint32_t r[4];
                ldmx4(r, sbase + OFF_BH + b_off + (uint32_t)(np * 16 * SROW) + ko);
                bhi[np * 2][0] = r[0]; bhi[np * 2 + 1][0] = r[1];
                bhi[np * 2][1] = r[2]; bhi[np * 2 + 1][1] = r[3];
                ldmx4(r, sbase + OFF_BL + b_off + (uint32_t)(np * 16 * SROW) + ko);
                blo[np * 2][0] = r[0]; blo[np * 2 + 1][0] = r[1];
                blo[np * 2][1] = r[2]; blo[np * 2 + 1][1] = r[3];
            }

            #pragma unroll
            for (int mt = 0; mt < 2; mt++)
                #pragma unroll
                for (int nt = 0; nt < 4; nt++)
                    imma16832(accH[mt][nt], a[mt], bhi[nt]);
            #pragma unroll
            for (int mt = 0; mt < 2; mt++)
                #pragma unroll
                for (int nt = 0; nt < 4; nt++)
                    imma16832(accL[mt][nt], a[mt], blo[nt]);
        }
        __syncthreads();
    }

    #pragma unroll
    for (int mt = 0; mt < 2; mt++) {
        const int row0 = bm + wm * 32 + mt * 16 + (l >> 2);
        const float rs0 = 1.0f / (float)deg[row0];
        const float rs1 = 1.0f / (float)deg[row0 + 8];
        float rm0 = 0.0f, rm1 = 0.0f;
        #pragma unroll
        for (int nt = 0; nt < 4; nt++) {
            const int col = bn + wn * 32 + nt * 8 + (l & 3) * 2;
            const float sb0 = sb[col], sb1 = sb[col + 1];
            const float bb0 = bias[col], bb1 = bias[col + 1];
            int c0 = accH[mt][nt][0] * 128 + accL[mt][nt][0];
            int c1 = accH[mt][nt][1] * 128 + accL[mt][nt][1];
            int c2 = accH[mt][nt][2] * 128 + accL[mt][nt][2];
            int c3 = accH[mt][nt][3] * 128 + accL[mt][nt][3];
            float v0 = (float)c0 * sb0 * rs0 + bb0;
            float v1 = (float)c1 * sb1 * rs0 + bb1;
            float v2 = (float)c2 * sb0 * rs1 + bb0;
            float v3 = (float)c3 * sb1 * rs1 + bb1;
            if (RELU) {
                v0 = fmaxf(v0, 0.0f); v1 = fmaxf(v1, 0.0f);
                v2 = fmaxf(v2, 0.0f); v3 = fmaxf(v3, 0.0f);
            }
            rm0 = fmaxf(rm0, fmaxf(fabsf(v0), fabsf(v1)));
            rm1 = fmaxf(rm1, fmaxf(fabsf(v2), fabsf(v3)));
            *(float2*)(C + (size_t)row0 * NC + col)       = make_float2(v0, v1);
            *(float2*)(C + (size_t)(row0 + 8) * NC + col) = make_float2(v2, v3);
        }
        if (amaxU) {
            atomicMax(amaxU + row0,     __float_as_uint(rm0));
            atomicMax(amaxU + row0 + 8, __float_as_uint(rm1));
        }
    }
}

// ===================== IMMA GEMM: C = A @ B^T -- 128x64 tiles, 2 CTAs/SM ===
__global__ __launch_bounds__(256, 2)
void gemm_AB(const int8_t* __restrict__ Ahi, const int8_t* __restrict__ Alo,
             const int8_t* __restrict__ Bhi, const int8_t* __restrict__ Blo,
             float* __restrict__ C, int Kb, int NC,
             const float* __restrict__ sa, const float* __restrict__ sbv,
             unsigned* __restrict__ cmaxU)
{
    extern __shared__ int8_t smem[];
    constexpr int SROW = 80;
    constexpr int ATILE = 128 * SROW;          // 10240
    constexpr int BTILE = 64 * SROW;           // 5120
    constexpr int OFF_AH = 0, OFF_AL = ATILE;
    constexpr int OFF_BH = 2 * ATILE, OFF_BL = 2 * ATILE + BTILE;
    constexpr int SS = 2 * ATILE + 2 * BTILE;  // 30720; x3 = 92160

    const int tid = threadIdx.x;
    const int w   = tid >> 5;
    const int l   = tid & 31;
    const int wm  = w >> 1;
    const int wn  = w & 1;
    const int bm  = blockIdx.y * 128;
    const int bn  = blockIdx.x * 64;
    const uint32_t smb = smem_u32(smem);

    auto load_stage = [&](int st, int k0) {
        const uint32_t sbase = smb + (uint32_t)st * SS;
        #pragma unroll
        for (int it = 0; it < 2; it++) {       // AH + AL: 128 rows each
            int idx = tid + it * 256;
            int r = idx >> 2, c = idx & 3;
            uint32_t so = (uint32_t)(r * SROW + c * 16);
            cp16(sbase + OFF_AH + so, Ahi + (size_t)(bm + r) * Kb + k0 + c * 16);
            cp16(sbase + OFF_AL + so, Alo + (size_t)(bm + r) * Kb + k0 + c * 16);
        }
        {                                      // BH + BL: 64 rows each
            int r = tid >> 2, c = tid & 3;
            uint32_t so = (uint32_t)(r * SROW + c * 16);
            cp16(sbase + OFF_BH + so, Bhi + (size_t)(bn + r) * Kb + k0 + c * 16);
            cp16(sbase + OFF_BL + so, Blo + (size_t)(bn + r) * Kb + k0 + c * 16);
        }
        CP_COMMIT();
    };

    int accHH[2][4][4], accM[2][4][4];
    #pragma unroll
    for (int i = 0; i < 2; i++)
        #pragma unroll
        for (int j = 0; j < 4; j++)
            #pragma unroll
            for (int e = 0; e < 4; e++) { accHH[i][j][e] = 0; accM[i][j][e] = 0; }

    const int NK = Kb >> 6;
    load_stage(0, 0);
    if (NK > 1) load_stage(1, 64);

    const uint32_t a_off = (uint32_t)((wm * 32 + (l & 15)) * SROW + (l >> 4) * 16);
    const uint32_t b_off = (uint32_t)((wn * 32 + (l & 15)) * SROW + (l >> 4) * 16);

    for (int kt = 0; kt < NK; kt++) {
        if (kt == NK - 1) { CP_WAIT0(); } else { CP_WAIT1(); }
        __syncthreads();
        if (kt + 2 < NK) load_stage((kt + 2) % 3, (kt + 2) << 6);

        const uint32_t sbase = smb + (uint32_t)((kt % 3) * SS);
        #pragma unroll
        for (int ks = 0; ks < 2; ks++) {
            const uint32_t ko = (uint32_t)ks * 32;
            uint32_t ahi[2][4], alo[2][4];
            #pragma unroll
            for (int mt = 0; mt < 2; mt++) {
                ldmx4(ahi[mt], sbase + OFF_AH + a_off + (uint32_t)(mt * 16 * SROW) + ko);
                ldmx4(alo[mt], sbase + OFF_AL + a_off + (uint32_t)(mt * 16 * SROW) + ko);
            }

            uint32_t bhi[4][2], blo[4][2];
            #pragma unroll
            for (int np = 0; np < 2; np++) {
                uint32_t r[4];
                ldmx4(r, sbase + OFF_BH + b_off + (uint32_t)(np * 16 * SROW) + ko);
                bhi[np * 2][0] = r[0]; bhi[np * 2 + 1][0] = r[1];
                bhi[np * 2][1] = r[2]; bhi[np * 2 + 1][1] = r[3];
                ldmx4(r, sbase + OFF_BL + b_off + (uint32_t)(np * 16 * SROW) + ko);
                blo[np * 2][0] = r[0]; blo[np * 2 + 1][0] = r[1];
                blo[np * 2][1] = r[2]; blo[np * 2 + 1][1] = r[3];
            }

            #pragma unroll
            for (int mt = 0; mt < 2; mt++)
                #pragma unroll
                for (int nt = 0; nt < 4; nt++)
                    imma16832(accHH[mt][nt], ahi[mt], bhi[nt]);
            #pragma unroll
            for (int mt = 0; mt < 2; mt++)
                #pragma unroll
                for (int nt = 0; nt < 4; nt++)
                    imma16832(accM[mt][nt], ahi[mt], blo[nt]);
            #pragma unroll
            for (int mt = 0; mt < 2; mt++)
                #pragma unroll
                for (int nt = 0; nt < 4; nt++)
                    imma16832(accM[mt][nt], alo[mt], bhi[nt]);
        }
        __syncthreads();
    }

    float cm[8];
    #pragma unroll
    for (int i = 0; i < 8; i++) cm[i] = 0.0f;

    #pragma unroll
    for (int mt = 0; mt < 2; mt++) {
        const int row0 = bm + wm * 32 + mt * 16 + (l >> 2);
        const float sa0 = sa[row0], sa1 = sa[row0 + 8];
        #pragma unroll
        for (int nt = 0; nt < 4; nt++) {
            const int col = bn + wn * 32 + nt * 8 + (l & 3) * 2;
            const float sb0 = sbv[col], sb1 = sbv[col + 1];
            float v0 = sa0 * sb0 * (16384.0f * (float)accHH[mt][nt][0] + 128.0f * (float)accM[mt][nt][0]);
            float v1 = sa0 * sb1 * (16384.0f * (float)accHH[mt][nt][1] + 128.0f * (float)accM[mt][nt][1]);
            float v2 = sa1 * sb0 * (16384.0f * (float)accHH[mt][nt][2] + 128.0f * (float)accM[mt][nt][2]);
            float v3 = sa1 * sb1 * (16384.0f * (float)accHH[mt][nt][3] + 128.0f * (float)accM[mt][nt][3]);
            cm[nt * 2]     = fmaxf(cm[nt * 2],     fmaxf(fabsf(v0), fabsf(v2)));
            cm[nt * 2 + 1] = fmaxf(cm[nt * 2 + 1], fmaxf(fabsf(v1), fabsf(v3)));
            *(float2*)(C + (size_t)row0 * NC + col)       = make_float2(v0, v1);
            *(float2*)(C + (size_t)(row0 + 8) * NC + col) = make_float2(v2, v3);
        }
    }
    if (cmaxU) {
        #pragma unroll
        for (int nt = 0; nt < 4; nt++) {
            const int col = bn + wn * 32 + nt * 8 + (l & 3) * 2;
            atomicMax(cmaxU + col,     __float_as_uint(cm[nt * 2]));
            atomicMax(cmaxU + col + 1, __float_as_uint(cm[nt * 2 + 1]));
        }
    }
}

// ===================== split-K FFMA sgemm (gc3, BK=32 coalesced) ===========
template<int V>
__device__ __forceinline__ void ldvec(float* d, const float* s) {
    if constexpr (V == 4) {
        *(float4*)d = *(const float4*)s;
    } else if constexpr (V == 2) {
        *(float2*)d = *(const float2*)s;
    } else {
        #pragma unroll
        for (int i = 0; i < V; i++) d[i] = s[i];
    }
}

template<int BM, int BN, int BK, int TM, int TN>
__global__ __launch_bounds__(256)
void sgemm_sk(const float* __restrict__ A, const float* __restrict__ B,
              float* __restrict__ C, int M, int N, int K, int lda)
{
    static_assert((BM / TM) * (BN / TN) == 256, "need 256 threads");
    constexpr int ALOAD = BM * BK / 256;
    constexpr int BLOAD = BK * BN / 256;

    __shared__ float As[2][BK * BM];
    __shared__ float Bs[2][BK * BN];

    const int s = blockIdx.z;
    A += (size_t)s * K;
    B += (size_t)s * K * N;
    C += (size_t)s * M * N;

    const int tid = threadIdx.x;
    const int bm  = blockIdx.y * BM;
    const int bn  = blockIdx.x * BN;
    const int tx  = tid % (BN / TN);
    const int ty  = tid / (BN / TN);

    #pragma unroll
    for (int l = 0; l < ALOAD; l++) {
        int idx = tid + l * 256;
        int r = idx / BK, c = idx % BK;
        As[0][c * BM + r] = A[(size_t)(bm + r) * lda + c];
    }
    #pragma unroll
    for (int l = 0; l < BLOAD; l++) {
        int idx = tid + l * 256;
        int r = idx / BN, c = idx % BN;
        Bs[0][r * BN + c] = B[(size_t)r * N + bn + c];
    }
    __syncthreads();

    float acc[TM * TN];
    #pragma unroll
    for (int i = 0; i < TM * TN; i++) acc[i] = 0.0f;

    float areg[ALOAD], breg[BLOAD];
    const int nk = K / BK;
    int st = 0;

    for (int kt = 0; kt < nk; kt++) {
        if (kt + 1 < nk) {
            const int k0 = (kt + 1) * BK;
            #pragma unroll
            for (int l = 0; l < ALOAD; l++) {
                int idx = tid + l * 256;
                int r = idx / BK, c = idx % BK;
                areg[l] = A[(size_t)(bm + r) * lda + k0 + c];
            }
            #pragma unroll
            for (int l = 0; l < BLOAD; l++) {
                int idx = tid + l * 256;
                int r = idx / BN, c = idx % BN;
                breg[l] = B[(size_t)(k0 + r) * N + bn + c];
            }
        }
        #pragma unroll
        for (int kk = 0; kk < BK; kk++) {
            float fa[TM], fb[TN];
            ldvec<TM>(fa, &As[st][kk * BM + ty * TM]);
            ldvec<TN>(fb, &Bs[st][kk * BN + tx * TN]);
            #pragma unroll
            for (int i = 0; i < TM; i++)
                #pragma unroll
                for (int j = 0; j < TN; j++)
                    acc[i * TN + j] += fa[i] * fb[j];
        }
        if (kt + 1 < nk) {
            st ^= 1;
            #pragma unroll
            for (int l = 0; l < ALOAD; l++) {
                int idx = tid + l * 256;
                int r = idx / BK, c = idx % BK;
                As[st][c * BM + r] = areg[l];
            }
            #pragma unroll
            for (int l = 0; l < BLOAD; l++) {
                int idx = tid + l * 256;
                int r = idx / BN, c = idx % BN;
                Bs[st][r * BN + c] = breg[l];
            }
            __syncthreads();
        }
    }

    const int row0 = bm + ty * TM;
    const int col0 = bn + tx * TN;
    #pragma unroll
    for (int i = 0; i < TM; i++)
        #pragma unroll
        for (int j = 0; j < TN; j++)
            C[(size_t)(row0 + i) * N + col0 + j] = acc[i * TN + j];
}

template<int MODE>
__global__ void sk_reduce(const float* __restrict__ part, int M, int S,
                          float* __restrict__ C, float* __restrict__ C2,
                          const int* __restrict__ deg, const float* __restrict__ bias) {
    int i = blockIdx.x * 256 + threadIdx.x;
    if (i >= M * CODE) return;
    int m = i >> 6, c = i & 63;
    float v = 0.0f;
    for (int s = 0; s < S; s++) v += part[(size_t)s * M * CODE + i];
    if (MODE == 3) {
        v = v * (1.0f / (float)deg[m]) + bias[c];
        C[i] = v;
        C2[i] = tanhf(v);
    } else {
        C[i] = v;
    }
}

// ===================== launch ==============================================
extern "C" void kernel_launch(void* const* d_in, const int* in_sizes, int n_in,
                              void* d_out, int out_size) {
    const float* x  = (const float*)d_in[0];
    const float* W1 = (const float*)d_in[1];
    const float* b1 = (const float*)d_in[2];
    const float* W2 = (const float*)d_in[3];
    const float* b2 = (const float*)d_in[4];
    const float* W3 = (const float*)d_in[5];
    const float* b3 = (const float*)d_in[6];

    void* p;
    float *w, *P, *F1, *P3, *part, *sb1, *sb2, *sw, *sa;
    int8_t *x8, *w8, *BThi, *BTlo, *Ahi, *Alo, *W2Thi, *W2Tlo;
    unsigned *mxP1, *mxP2, *mxW, *amaxU;
    int* deg;
    cudaGetSymbolAddress(&p, g_x8);    x8    = (int8_t*)p;
    cudaGetSymbolAddress(&p, g_w);     w     = (float*)p;
    cudaGetSymbolAddress(&p, g_w8);    w8    = (int8_t*)p;
    cudaGetSymbolAddress(&p, g_deg);   deg   = (int*)p;
    cudaGetSymbolAddress(&p, g_P);     P     = (float*)p;
    cudaGetSymbolAddress(&p, g_F1);    F1    = (float*)p;
    cudaGetSymbolAddress(&p, g_P3);    P3    = (float*)p;
    cudaGetSymbolAddress(&p, g_part);  part  = (float*)p;
    cudaGetSymbolAddress(&p, g_BThi);  BThi  = (int8_t*)p;
    cudaGetSymbolAddress(&p, g_BTlo);  BTlo  = (int8_t*)p;
    cudaGetSymbolAddress(&p, g_Ahi);   Ahi   = (int8_t*)p;
    cudaGetSymbolAddress(&p, g_Alo);   Alo   = (int8_t*)p;
    cudaGetSymbolAddress(&p, g_W2Thi); W2Thi = (int8_t*)p;
    cudaGetSymbolAddress(&p, g_W2Tlo); W2Tlo = (int8_t*)p;
    cudaGetSymbolAddress(&p, g_mxP1);  mxP1  = (unsigned*)p;
    cudaGetSymbolAddress(&p, g_mxP2);  mxP2  = (unsigned*)p;
    cudaGetSymbolAddress(&p, g_mxW);   mxW   = (unsigned*)p;
    cudaGetSymbolAddress(&p, g_sb1);   sb1   = (float*)p;
    cudaGetSymbolAddress(&p, g_sb2);   sb2   = (float*)p;
    cudaGetSymbolAddress(&p, g_sw);    sw    = (float*)p;
    cudaGetSymbolAddress(&p, g_sa);    sa    = (float*)p;
    cudaGetSymbolAddress(&p, g_amax);  amaxU = (unsigned*)p;

    float* featOut = (float*)d_out;
    float* hidOut  = featOut + (size_t)N_NODES * HIDD;
    float* codeOut = hidOut  + (size_t)N_NODES * CODE;

    constexpr int SMEM_ADJ = 2 * 2 * 128 * 80;  // 40960
    constexpr int SMEM_WB  = 3 * (128 + 2 * 64) * 80;   // 61440
    constexpr int SMEM_AB  = 3 * (2 * 128 + 2 * 64) * 80; // 92160
    cudaFuncSetAttribute(gemm_adj,       cudaFuncAttributeMaxDynamicSharedMemorySize, SMEM_ADJ);
    cudaFuncSetAttribute(gemm_wB<false>, cudaFuncAttributeMaxDynamicSharedMemorySize, SMEM_WB);
    cudaFuncSetAttribute(gemm_wB<true>,  cudaFuncAttributeMaxDynamicSharedMemorySize, SMEM_WB);
    cudaFuncSetAttribute(gemm_AB,        cudaFuncAttributeMaxDynamicSharedMemorySize, SMEM_AB);

    // fused prep + adjacency (exact IMMA)
    prep_all<<<(N_NODES * KPAD + 255) / 256, 256>>>(x);
    gemm_adj<<<dim3(N_NODES / 128, N_NODES / 128), 256, SMEM_ADJ>>>(x8, w, w8, deg);

    // W2 quantization
    colmax<<<dim3(HIDD / 256, 16), 256>>>(W2, HIDD, HIDD, mxW);
    quantT<<<dim3(HIDD / 32, HIDD / 128), 256>>>(W2, HIDD, HIDD, mxW, W2Thi, W2Tlo, sw);

    // gc1: P1 = x@W1 (fused colmax) ; quantize P1^T ; feat1 = (w@P1)/deg+b1 (fused rowmax)
    xw1_kernel<<<N_NODES, 256>>>(W1);
    quantT<<<dim3(HIDD / 32, N_NODES / 128), 256>>>(P, N_NODES, HIDD, mxP1, BThi, BTlo, sb1);
    gemm_wB<false><<<dim3(HIDD / 64, N_NODES / 128), 256, SMEM_WB>>>(
        w8, BThi, BTlo, F1, N_NODES, HIDD, sb1, deg, b1, amaxU);

    // gc2: quantize feat1 rows ; P2 = f1q@W2q (fused colmax) ; quantize P2^T ;
    //      feat = relu((w@P2)/deg+b2) -> d_out
    quantA<<<(N_NODES * HIDD / 4 + 255) / 256, 256>>>(F1, amaxU, Ahi, Alo, sa);
    gemm_AB<<<dim3(HIDD / 64, N_NODES / 128), 256, SMEM_AB>>>(
        Ahi, Alo, W2Thi, W2Tlo, P, HIDD, HIDD, sa, sw, mxP2);
    quantT<<<dim3(HIDD / 32, N_NODES / 128), 256>>>(P, N_NODES, HIDD, mxP2, BThi, BTlo, sb2);
    gemm_wB<true><<<dim3(HIDD / 64, N_NODES / 128), 256, SMEM_WB>>>(
        w8, BThi, BTlo, featOut, N_NODES, HIDD, sb2, deg, b2, nullptr);

    // gc3 (fp32 split-K)
    sgemm_sk<64, 64, 32, 4, 4><<<dim3(1, N_NODES / 64, 8), 256>>>(
        featOut, W3, part, N_NODES, CODE, HIDD / 8, HIDD);
    sk_reduce<0><<<(N_NODES * CODE + 255) / 256, 256>>>(
        part, N_NODES, 8, P3, nullptr, nullptr, nullptr);
    sgemm_sk<64, 64, 32, 4, 4><<<dim3(1, N_NODES / 64, 8), 256>>>(
        w, P3, part, N_NODES, CODE, N_NODES / 8, N_NODES);
    sk_reduce<3><<<(N_NODES * CODE + 255) / 256, 256>>>(
        part, N_NODES, 8, hidOut, codeOut, deg, b3);
}